// round 3
// baseline (speedup 1.0000x reference)
#include <cuda_runtime.h>
#include <math.h>

// Problem constants (fixed by the reference)
#define Nn   50000
#define Ee   800000
#define IOd  128
#define HIDd 256
#define KQd  256

// ---------------- device scratch (no allocations allowed) ----------------
__device__ float g_q[Nn * KQd];
__device__ float g_k[Nn * KQd];
__device__ float g_v[Nn * HIDd];
__device__ float g_r[Nn * HIDd];
__device__ float g_h[Nn * HIDd];    // conv output (agg + r + b)
__device__ float g_x1[Nn * HIDd];   // layer1 post BN+relu
__device__ float g_elog[Ee];        // per-edge logits at CSR positions
__device__ int   g_src[Ee];
__device__ int   g_dst[Ee];
__device__ int   g_csr_src[Ee];     // src ids grouped by dst
__device__ int   g_deg[Nn];
__device__ int   g_inc[Nn];         // inclusive prefix of deg
__device__ int   g_fill[Nn];
#define NB_SCAN 49                  // ceil(50000/1024)
__device__ int   g_bsum[NB_SCAN];
__device__ int   g_boff[NB_SCAN];
__device__ double g_sumd[HIDd];
__device__ double g_sumsqd[HIDd];
__device__ float g_mean[HIDd];
__device__ float g_inv[HIDd];
__device__ int   g_flag64[1];

// ---------------- edge dtype detection + conversion ----------------
__global__ void detect_edges_kernel(const int* __restrict__ ew) {
    __shared__ int nz;
    if (threadIdx.x == 0) nz = 0;
    __syncthreads();
    int stride = Ee / 256;
    int idx = 2 * (threadIdx.x * stride) + 1;
    if (ew[idx] != 0) atomicOr(&nz, 1);
    __syncthreads();
    if (threadIdx.x == 0) g_flag64[0] = nz ? 0 : 1;
}

__global__ void convert_edges_kernel(const void* __restrict__ edges) {
    int e = blockIdx.x * blockDim.x + threadIdx.x;
    if (e >= Ee) return;
    if (g_flag64[0]) {
        const long long* p = (const long long*)edges;
        g_src[e] = (int)p[e];
        g_dst[e] = (int)p[Ee + e];
    } else {
        const int* p = (const int*)edges;
        g_src[e] = p[e];
        g_dst[e] = p[Ee + e];
    }
}

// ---------------- CSR build ----------------
__global__ void csr_zero_kernel() {
    int i = blockIdx.x * blockDim.x + threadIdx.x;
    if (i < Nn) { g_deg[i] = 0; g_fill[i] = 0; }
}
__global__ void csr_count_kernel() {
    int e = blockIdx.x * blockDim.x + threadIdx.x;
    if (e < Ee) atomicAdd(&g_deg[g_dst[e]], 1);
}
__global__ void scan1_kernel() {
    __shared__ int sm[1024];
    int i = blockIdx.x * 1024 + threadIdx.x;
    int v = (i < Nn) ? g_deg[i] : 0;
    sm[threadIdx.x] = v;
    __syncthreads();
    for (int off = 1; off < 1024; off <<= 1) {
        int t = (threadIdx.x >= off) ? sm[threadIdx.x - off] : 0;
        __syncthreads();
        sm[threadIdx.x] += t;
        __syncthreads();
    }
    if (i < Nn) g_inc[i] = sm[threadIdx.x];
    if (threadIdx.x == 1023) g_bsum[blockIdx.x] = sm[1023];
}
__global__ void scan2_kernel() {
    int acc = 0;
    for (int b = 0; b < NB_SCAN; b++) { g_boff[b] = acc; acc += g_bsum[b]; }
}
__global__ void scan3_kernel() {
    int i = blockIdx.x * 1024 + threadIdx.x;
    if (i < Nn) g_inc[i] += g_boff[blockIdx.x];
}
__global__ void csr_scatter_kernel() {
    int e = blockIdx.x * blockDim.x + threadIdx.x;
    if (e >= Ee) return;
    int d = g_dst[e];
    int pos = g_inc[d] - g_deg[d] + atomicAdd(&g_fill[d], 1);
    g_csr_src[pos] = g_src[e];
}

// ---------------- SGEMM: C[M,Nc] = A[M,K] @ B[K,Nc], fp32 ----------------
#define BM 64
#define BN 64
#define BK 32

__global__ __launch_bounds__(256) void sgemm_kernel(
    const float* __restrict__ A, const float* __restrict__ B,
    float* __restrict__ C, int M, int K, int Nc)
{
    __shared__ float As[BM][BK];
    __shared__ float Bs[BK][BN];

    const int m0 = blockIdx.y * BM;
    const int n0 = blockIdx.x * BN;
    const int tid = threadIdx.x;
    const int tx = tid & 15;
    const int ty = tid >> 4;
    const int ty4 = ty * 4;

    float acc[4][4] = {};

    for (int k0 = 0; k0 < K; k0 += BK) {
        #pragma unroll
        for (int i = 0; i < 2; i++) {
            int idx = tid + i * 256;
            int ar = idx >> 3;
            int ac = (idx & 7) * 4;
            float4 va = make_float4(0.f, 0.f, 0.f, 0.f);
            int row = m0 + ar;
            if (row < M)
                va = *(const float4*)(A + (size_t)row * K + k0 + ac);
            *(float4*)(&As[ar][ac]) = va;

            int br = idx >> 4;
            int bc = (idx & 15) * 4;
            float4 vb = *(const float4*)(B + (size_t)(k0 + br) * Nc + n0 + bc);
            *(float4*)(&Bs[br][bc]) = vb;
        }
        __syncthreads();

        #pragma unroll
        for (int kk = 0; kk < BK; kk++) {
            float a0 = As[ty4 + 0][kk];
            float a1 = As[ty4 + 1][kk];
            float a2 = As[ty4 + 2][kk];
            float a3 = As[ty4 + 3][kk];
            float4 bq = *(const float4*)(&Bs[kk][tx * 4]);
            acc[0][0] += a0 * bq.x; acc[0][1] += a0 * bq.y; acc[0][2] += a0 * bq.z; acc[0][3] += a0 * bq.w;
            acc[1][0] += a1 * bq.x; acc[1][1] += a1 * bq.y; acc[1][2] += a1 * bq.z; acc[1][3] += a1 * bq.w;
            acc[2][0] += a2 * bq.x; acc[2][1] += a2 * bq.y; acc[2][2] += a2 * bq.z; acc[2][3] += a2 * bq.w;
            acc[3][0] += a3 * bq.x; acc[3][1] += a3 * bq.y; acc[3][2] += a3 * bq.z; acc[3][3] += a3 * bq.w;
        }
        __syncthreads();
    }

    #pragma unroll
    for (int i = 0; i < 4; i++) {
        int row = m0 + ty4 + i;
        if (row < M) {
            float4 o = make_float4(acc[i][0], acc[i][1], acc[i][2], acc[i][3]);
            *(float4*)(C + (size_t)row * Nc + n0 + tx * 4) = o;
        }
    }
}

// ---------------- warp-per-node attention + aggregation ----------------
__device__ __forceinline__ float4 f4_fma(float s, float4 a, float4 acc) {
    acc.x += s * a.x; acc.y += s * a.y; acc.z += s * a.z; acc.w += s * a.w;
    return acc;
}

template <int F>
__global__ __launch_bounds__(256) void attn_kernel(const float* __restrict__ bias) {
    int n = (blockIdx.x * blockDim.x + threadIdx.x) >> 5;
    int lane = threadIdx.x & 31;
    if (n >= Nn) return;

    int deg = g_deg[n];
    int base = g_inc[n] - deg;

    const float4* q4 = (const float4*)g_q;
    const float4* k4 = (const float4*)g_k;
    const float4* v4 = (const float4*)g_v;
    const float4* r4 = (const float4*)g_r;
    const float4* b4 = (const float4*)bias;
    float4* h4 = (float4*)g_h;

    float4 acc0 = make_float4(0.f, 0.f, 0.f, 0.f);
    float4 acc1 = make_float4(0.f, 0.f, 0.f, 0.f);
    float ssum = 0.f;

    if (deg > 0) {
        float4 q0 = q4[(size_t)n * 64 + lane];
        float4 q1 = q4[(size_t)n * 64 + 32 + lane];
        float mx = -INFINITY;
        for (int j = 0; j < deg; j++) {
            int s = g_csr_src[base + j];
            float4 k0 = k4[(size_t)s * 64 + lane];
            float4 k1 = k4[(size_t)s * 64 + 32 + lane];
            float p = q0.x * k0.x + q0.y * k0.y + q0.z * k0.z + q0.w * k0.w
                    + q1.x * k1.x + q1.y * k1.y + q1.z * k1.z + q1.w * k1.w;
            #pragma unroll
            for (int off = 16; off; off >>= 1)
                p += __shfl_xor_sync(0xffffffffu, p, off);
            p *= 0.0625f;     // 1/sqrt(256)
            if (lane == 0) g_elog[base + j] = p;
            mx = fmaxf(mx, p);
        }
        __syncwarp();
        for (int j = 0; j < deg; j++) {
            int s = g_csr_src[base + j];
            float e = expf(g_elog[base + j] - mx);
            ssum += e;
            if (F == 256) {
                acc0 = f4_fma(e, v4[(size_t)s * 64 + lane], acc0);
                acc1 = f4_fma(e, v4[(size_t)s * 64 + 32 + lane], acc1);
            } else {
                acc0 = f4_fma(e, v4[(size_t)s * 32 + lane], acc0);
            }
        }
    }

    float inv = (deg > 0) ? 1.f / fmaxf(ssum, 1e-16f) : 0.f;
    if (F == 256) {
        size_t o = (size_t)n * 64;
        float4 rr = r4[o + lane], bb = b4[lane];
        h4[o + lane] = make_float4(acc0.x * inv + rr.x + bb.x, acc0.y * inv + rr.y + bb.y,
                                   acc0.z * inv + rr.z + bb.z, acc0.w * inv + rr.w + bb.w);
        rr = r4[o + 32 + lane]; bb = b4[32 + lane];
        h4[o + 32 + lane] = make_float4(acc1.x * inv + rr.x + bb.x, acc1.y * inv + rr.y + bb.y,
                                        acc1.z * inv + rr.z + bb.z, acc1.w * inv + rr.w + bb.w);
    } else {
        size_t o = (size_t)n * 32;
        float4 rr = r4[o + lane], bb = b4[lane];
        h4[o + lane] = make_float4(acc0.x * inv + rr.x + bb.x, acc0.y * inv + rr.y + bb.y,
                                   acc0.z * inv + rr.z + bb.z, acc0.w * inv + rr.w + bb.w);
    }
}

// ---------------- batch norm (double accumulation) ----------------
__global__ void bn_zero_kernel() {
    int f = threadIdx.x;
    g_sumd[f] = 0.0; g_sumsqd[f] = 0.0;
}
#define BN_ROWS 256
__global__ __launch_bounds__(256) void bn_stats_kernel(int F) {
    int r0 = blockIdx.x * BN_ROWS;
    int r1 = min(r0 + BN_ROWS, Nn);
    for (int f = threadIdx.x; f < F; f += 256) {
        double s = 0.0, q = 0.0;
        for (int r = r0; r < r1; r++) {
            float v = g_h[(size_t)r * F + f];
            s += (double)v; q += (double)v * (double)v;
        }
        atomicAdd(&g_sumd[f], s);
        atomicAdd(&g_sumsqd[f], q);
    }
}
__global__ void bn_finalize_kernel(int F) {
    int f = threadIdx.x;
    if (f < F) {
        double mu = g_sumd[f] / (double)Nn;
        double var = g_sumsqd[f] / (double)Nn - mu * mu;
        if (var < 0.0) var = 0.0;
        g_mean[f] = (float)mu;
        g_inv[f] = (float)(1.0 / sqrt(var + 1e-5));
    }
}
__global__ void bn_apply_relu_kernel(const float* __restrict__ gam,
                                     const float* __restrict__ bet, int F) {
    int i = blockIdx.x * blockDim.x + threadIdx.x;
    if (i < Nn * F) {
        int f = i % F;
        float v = (g_h[i] - g_mean[f]) * g_inv[f] * gam[f] + bet[f];
        g_x1[i] = v > 0.f ? v : 0.f;
    }
}
__global__ void final_out_kernel(const float* __restrict__ gam,
                                 const float* __restrict__ bet,
                                 const float* __restrict__ x0,
                                 float* __restrict__ out) {
    int i = blockIdx.x * blockDim.x + threadIdx.x;
    if (i < Nn * IOd) {
        int f = i % IOd;
        float v = (g_h[i] - g_mean[f]) * g_inv[f] * gam[f] + bet[f] + x0[i];
        out[i] = v > 0.f ? v : 0.f;
    }
}

// ---------------- launch sequence ----------------
extern "C" void kernel_launch(void* const* d_in, const int* in_sizes, int n_in,
                              void* d_out, int out_size) {
    const float* x0  = (const float*)d_in[0];
    const void*  edg = d_in[1];
    const float* Wq1 = (const float*)d_in[2];
    const float* Wk1 = (const float*)d_in[3];
    const float* Wv1 = (const float*)d_in[4];
    const float* Wr1 = (const float*)d_in[5];
    const float* b1  = (const float*)d_in[6];
    const float* g1  = (const float*)d_in[7];
    const float* be1 = (const float*)d_in[8];
    const float* Wq2 = (const float*)d_in[9];
    const float* Wk2 = (const float*)d_in[10];
    const float* Wv2 = (const float*)d_in[11];
    const float* Wr2 = (const float*)d_in[12];
    const float* b2  = (const float*)d_in[13];
    const float* g2  = (const float*)d_in[14];
    const float* be2 = (const float*)d_in[15];
    float* out = (float*)d_out;

    // CRITICAL: resolve real device addresses of __device__ globals.
    // (Passing the symbol directly from host hands the kernel the host
    //  shadow address; on GB300 ATS makes that a silent write to host RAM.)
    float *pq, *pk, *pv, *pr, *px1;
    cudaGetSymbolAddress((void**)&pq,  g_q);
    cudaGetSymbolAddress((void**)&pk,  g_k);
    cudaGetSymbolAddress((void**)&pv,  g_v);
    cudaGetSymbolAddress((void**)&pr,  g_r);
    cudaGetSymbolAddress((void**)&px1, g_x1);

    const int EDGE_BLOCKS = (Ee + 255) / 256;
    const int NODE_BLOCKS = (Nn + 255) / 256;
    const int NH_BLOCKS = (Nn * HIDd + 255) / 256;
    const int NI_BLOCKS = (Nn * IOd + 255) / 256;
    const int BN_BLOCKS = (Nn + BN_ROWS - 1) / BN_ROWS;
    const int ATTN_BLOCKS = (Nn * 32 + 255) / 256;

    detect_edges_kernel<<<1, 256>>>((const int*)edg);
    convert_edges_kernel<<<EDGE_BLOCKS, 256>>>(edg);

    csr_zero_kernel<<<NODE_BLOCKS, 256>>>();
    csr_count_kernel<<<EDGE_BLOCKS, 256>>>();
    scan1_kernel<<<NB_SCAN, 1024>>>();
    scan2_kernel<<<1, 1>>>();
    scan3_kernel<<<NB_SCAN, 1024>>>();
    csr_scatter_kernel<<<EDGE_BLOCKS, 256>>>();

    // ---- layer 1 (Kin=128) ----
    {
        dim3 gqk(KQd / BN, (Nn + BM - 1) / BM);
        dim3 gvh(HIDd / BN, (Nn + BM - 1) / BM);
        sgemm_kernel<<<gqk, 256>>>(x0, Wq1, pq, Nn, IOd, KQd);
        sgemm_kernel<<<gqk, 256>>>(x0, Wk1, pk, Nn, IOd, KQd);
        sgemm_kernel<<<gvh, 256>>>(x0, Wv1, pv, Nn, IOd, HIDd);
        sgemm_kernel<<<gvh, 256>>>(x0, Wr1, pr, Nn, IOd, HIDd);

        attn_kernel<256><<<ATTN_BLOCKS, 256>>>(b1);

        bn_zero_kernel<<<1, 256>>>();
        bn_stats_kernel<<<BN_BLOCKS, 256>>>(HIDd);
        bn_finalize_kernel<<<1, 256>>>(HIDd);
        bn_apply_relu_kernel<<<NH_BLOCKS, 256>>>(g1, be1, HIDd);
    }

    // ---- layer 2 (Kin=256) ----
    {
        dim3 gqk(KQd / BN, (Nn + BM - 1) / BM);
        dim3 gio(IOd / BN, (Nn + BM - 1) / BM);
        sgemm_kernel<<<gqk, 256>>>(px1, Wq2, pq, Nn, HIDd, KQd);
        sgemm_kernel<<<gqk, 256>>>(px1, Wk2, pk, Nn, HIDd, KQd);
        sgemm_kernel<<<gio, 256>>>(px1, Wv2, pv, Nn, HIDd, IOd);
        sgemm_kernel<<<gio, 256>>>(px1, Wr2, pr, Nn, HIDd, IOd);

        attn_kernel<128><<<ATTN_BLOCKS, 256>>>(b2);

        bn_zero_kernel<<<1, 256>>>();
        bn_stats_kernel<<<BN_BLOCKS, 256>>>(IOd);
        bn_finalize_kernel<<<1, 256>>>(IOd);
        final_out_kernel<<<NI_BLOCKS, 256>>>(g2, be2, x0, out);
    }
}

// round 5
// speedup vs baseline: 1.6495x; 1.6495x over previous
#include <cuda_runtime.h>
#include <math.h>
#include <stdint.h>

// Problem constants (fixed by the reference)
#define Nn   50000
#define Ee   800000
#define IOd  128
#define HIDd 256
#define KQd  256

// ---------------- device scratch (no allocations allowed) ----------------
__device__ float g_q[Nn * KQd];
__device__ float g_k[Nn * KQd];
__device__ float g_v[Nn * HIDd];
__device__ float g_r[Nn * HIDd];
__device__ float g_h[Nn * HIDd];
__device__ float g_x1[Nn * HIDd];
__device__ float g_elog[Ee];
__device__ float g_wt[327680];      // transposed weights
__device__ int   g_src[Ee];
__device__ int   g_dst[Ee];
__device__ int   g_csr_src[Ee];
__device__ int   g_deg[Nn];
__device__ int   g_inc[Nn];
__device__ int   g_fill[Nn];
#define NB_SCAN 49
__device__ int   g_bsum[NB_SCAN];
__device__ int   g_boff[NB_SCAN];
__device__ double g_sumd[HIDd];
__device__ double g_sumsqd[HIDd];
__device__ float g_mean[HIDd];
__device__ float g_inv[HIDd];
__device__ int   g_flag64[1];

// transposed-weight offsets in g_wt
#define WT_Q1 0
#define WT_K1 32768
#define WT_V1 65536
#define WT_R1 98304
#define WT_Q2 131072
#define WT_K2 196608
#define WT_V2 262144
#define WT_R2 294912

// ---------------- helpers ----------------
__device__ __forceinline__ uint32_t smem_u32(const void* p) {
    uint32_t a;
    asm("{ .reg .u64 t; cvta.to.shared.u64 t, %1; cvt.u32.u64 %0, t; }" : "=r"(a) : "l"(p));
    return a;
}
__device__ __forceinline__ void cp_async16(uint32_t sm, const void* g) {
    asm volatile("cp.async.cg.shared.global [%0], [%1], 16;" :: "r"(sm), "l"(g));
}
__device__ __forceinline__ void cp_commit() { asm volatile("cp.async.commit_group;"); }
__device__ __forceinline__ void cp_wait1() { asm volatile("cp.async.wait_group 1;"); }
__device__ __forceinline__ void cp_wait0() { asm volatile("cp.async.wait_group 0;"); }

// ---------------- weight transpose: Wt[n*K+k] = W[k*N+n] ----------------
__global__ void transpose_kernel(const float* __restrict__ W, float* __restrict__ Wt,
                                 int K, int N) {
    int i = blockIdx.x * 256 + threadIdx.x;
    if (i < K * N) {
        int k = i / N, n = i % N;
        Wt[n * K + k] = W[i];
    }
}

// ---------------- HMMA tf32 GEMM: C[M,N] = A[M,K] @ Bt[N,K]^T --------------
// CTA tile 128x128, 8 warps (2 M x 4 N), warp tile 64x32.
// mma.m16n8k8: per warp 4 mfrags x 4 nfrags x (4 ksteps of 8).
#define SROW 36   // padded smem row stride (floats); 36*4=144B, 16B aligned

template <int K, int N>
__global__ __launch_bounds__(256) void mma_gemm_kernel(
    const float* __restrict__ A, const float* __restrict__ Bt,
    float* __restrict__ C, int M)
{
    extern __shared__ float smem[];
    float* As = smem;                    // 2 x 128 x SROW
    float* Bs = smem + 2 * 128 * SROW;   // 2 x 128 x SROW

    const int tid = threadIdx.x;
    const int wid = tid >> 5;
    const int lane = tid & 31;
    const int gID = lane >> 2;       // 0..7
    const int tig = lane & 3;        // 0..3
    const int wm = (wid & 1) * 64;   // warp M offset in tile
    const int wn = (wid >> 1) * 32;  // warp N offset in tile
    const int m0 = blockIdx.x * 128;
    const int n0 = blockIdx.y * 128;

    float c[4][4][4] = {};

    constexpr int NC = K / 32;

    auto stage = [&](int cc, int buf) {
        const int k0 = cc * 32;
        float* ab = As + buf * (128 * SROW);
        float* bb = Bs + buf * (128 * SROW);
        #pragma unroll
        for (int i = 0; i < 4; i++) {            // A: 128 rows x 32 floats
            int idx = tid + i * 256;             // 0..1023
            int row = idx >> 3, g = idx & 7;
            int gr = m0 + row; if (gr >= M) gr = M - 1;
            cp_async16(smem_u32(ab + row * SROW + g * 4), A + (size_t)gr * K + k0 + g * 4);
        }
        #pragma unroll
        for (int i = 0; i < 4; i++) {            // B: 128 rows (n) x 32 floats (k)
            int idx = tid + i * 256;
            int row = idx >> 3, g = idx & 7;
            cp_async16(smem_u32(bb + row * SROW + g * 4), Bt + (size_t)(n0 + row) * K + k0 + g * 4);
        }
        cp_commit();
    };

    stage(0, 0);
    for (int cc = 0; cc < NC; cc++) {
        const int buf = cc & 1;
        if (cc + 1 < NC) { stage(cc + 1, buf ^ 1); cp_wait1(); }
        else             { cp_wait0(); }
        __syncthreads();

        const float* ab = As + buf * (128 * SROW);
        const float* bb = Bs + buf * (128 * SROW);

        #pragma unroll
        for (int ks = 0; ks < 4; ks++) {
            const int kk = ks * 8;
            uint32_t af[4][4];
            #pragma unroll
            for (int mf = 0; mf < 4; mf++) {
                const float* base = ab + (wm + mf * 16) * SROW + kk;
                af[mf][0] = __float_as_uint(base[gID * SROW + tig]);
                af[mf][1] = __float_as_uint(base[(gID + 8) * SROW + tig]);
                af[mf][2] = __float_as_uint(base[gID * SROW + tig + 4]);
                af[mf][3] = __float_as_uint(base[(gID + 8) * SROW + tig + 4]);
            }
            uint32_t bf[4][2];
            #pragma unroll
            for (int nf = 0; nf < 4; nf++) {
                const float* base = bb + (wn + nf * 8 + gID) * SROW + kk;
                bf[nf][0] = __float_as_uint(base[tig]);
                bf[nf][1] = __float_as_uint(base[tig + 4]);
            }
            #pragma unroll
            for (int mf = 0; mf < 4; mf++)
                #pragma unroll
                for (int nf = 0; nf < 4; nf++)
                    asm volatile(
                        "mma.sync.aligned.m16n8k8.row.col.f32.tf32.tf32.f32 "
                        "{%0,%1,%2,%3}, {%4,%5,%6,%7}, {%8,%9}, {%0,%1,%2,%3};"
                        : "+f"(c[mf][nf][0]), "+f"(c[mf][nf][1]),
                          "+f"(c[mf][nf][2]), "+f"(c[mf][nf][3])
                        : "r"(af[mf][0]), "r"(af[mf][1]), "r"(af[mf][2]), "r"(af[mf][3]),
                          "r"(bf[nf][0]), "r"(bf[nf][1]));
        }
        __syncthreads();
    }

    // epilogue: c0,c1 -> (row, col..col+1); c2,c3 -> (row+8, ...)
    #pragma unroll
    for (int mf = 0; mf < 4; mf++) {
        int row = m0 + wm + mf * 16 + gID;
        #pragma unroll
        for (int nf = 0; nf < 4; nf++) {
            int col = n0 + wn + nf * 8 + tig * 2;
            if (row < M)
                *(float2*)(C + (size_t)row * N + col) = make_float2(c[mf][nf][0], c[mf][nf][1]);
            if (row + 8 < M)
                *(float2*)(C + (size_t)(row + 8) * N + col) = make_float2(c[mf][nf][2], c[mf][nf][3]);
        }
    }
}

// ---------------- edge dtype detection + conversion ----------------
__global__ void detect_edges_kernel(const int* __restrict__ ew) {
    __shared__ int nz;
    if (threadIdx.x == 0) nz = 0;
    __syncthreads();
    int stride = Ee / 256;
    int idx = 2 * (threadIdx.x * stride) + 1;
    if (ew[idx] != 0) atomicOr(&nz, 1);
    __syncthreads();
    if (threadIdx.x == 0) g_flag64[0] = nz ? 0 : 1;
}

__global__ void convert_edges_kernel(const void* __restrict__ edges) {
    int e = blockIdx.x * blockDim.x + threadIdx.x;
    if (e >= Ee) return;
    if (g_flag64[0]) {
        const long long* p = (const long long*)edges;
        g_src[e] = (int)p[e];
        g_dst[e] = (int)p[Ee + e];
    } else {
        const int* p = (const int*)edges;
        g_src[e] = p[e];
        g_dst[e] = p[Ee + e];
    }
}

// ---------------- CSR build ----------------
__global__ void csr_zero_kernel() {
    int i = blockIdx.x * blockDim.x + threadIdx.x;
    if (i < Nn) { g_deg[i] = 0; g_fill[i] = 0; }
}
__global__ void csr_count_kernel() {
    int e = blockIdx.x * blockDim.x + threadIdx.x;
    if (e < Ee) atomicAdd(&g_deg[g_dst[e]], 1);
}
__global__ void scan1_kernel() {
    __shared__ int sm[1024];
    int i = blockIdx.x * 1024 + threadIdx.x;
    int v = (i < Nn) ? g_deg[i] : 0;
    sm[threadIdx.x] = v;
    __syncthreads();
    for (int off = 1; off < 1024; off <<= 1) {
        int t = (threadIdx.x >= off) ? sm[threadIdx.x - off] : 0;
        __syncthreads();
        sm[threadIdx.x] += t;
        __syncthreads();
    }
    if (i < Nn) g_inc[i] = sm[threadIdx.x];
    if (threadIdx.x == 1023) g_bsum[blockIdx.x] = sm[1023];
}
__global__ void scan2_kernel() {
    int acc = 0;
    for (int b = 0; b < NB_SCAN; b++) { g_boff[b] = acc; acc += g_bsum[b]; }
}
__global__ void scan3_kernel() {
    int i = blockIdx.x * 1024 + threadIdx.x;
    if (i < Nn) g_inc[i] += g_boff[blockIdx.x];
}
__global__ void csr_scatter_kernel() {
    int e = blockIdx.x * blockDim.x + threadIdx.x;
    if (e >= Ee) return;
    int d = g_dst[e];
    int pos = g_inc[d] - g_deg[d] + atomicAdd(&g_fill[d], 1);
    g_csr_src[pos] = g_src[e];
}

// ---------------- warp-per-node attention + aggregation ----------------
__device__ __forceinline__ float4 f4_fma(float s, float4 a, float4 acc) {
    acc.x += s * a.x; acc.y += s * a.y; acc.z += s * a.z; acc.w += s * a.w;
    return acc;
}

template <int F>
__global__ __launch_bounds__(256) void attn_kernel(const float* __restrict__ bias) {
    int n = (blockIdx.x * blockDim.x + threadIdx.x) >> 5;
    int lane = threadIdx.x & 31;
    if (n >= Nn) return;

    int deg = g_deg[n];
    int base = g_inc[n] - deg;

    const float4* q4 = (const float4*)g_q;
    const float4* k4 = (const float4*)g_k;
    const float4* v4 = (const float4*)g_v;
    const float4* r4 = (const float4*)g_r;
    const float4* b4 = (const float4*)bias;
    float4* h4 = (float4*)g_h;

    float4 acc0 = make_float4(0.f, 0.f, 0.f, 0.f);
    float4 acc1 = make_float4(0.f, 0.f, 0.f, 0.f);
    float ssum = 0.f;

    if (deg > 0) {
        float4 q0 = q4[(size_t)n * 64 + lane];
        float4 q1 = q4[(size_t)n * 64 + 32 + lane];
        float mx = -INFINITY;
        for (int j = 0; j < deg; j++) {
            int s = g_csr_src[base + j];
            float4 k0 = k4[(size_t)s * 64 + lane];
            float4 k1 = k4[(size_t)s * 64 + 32 + lane];
            float p = q0.x * k0.x + q0.y * k0.y + q0.z * k0.z + q0.w * k0.w
                    + q1.x * k1.x + q1.y * k1.y + q1.z * k1.z + q1.w * k1.w;
            #pragma unroll
            for (int off = 16; off; off >>= 1)
                p += __shfl_xor_sync(0xffffffffu, p, off);
            p *= 0.0625f;
            if (lane == 0) g_elog[base + j] = p;
            mx = fmaxf(mx, p);
        }
        __syncwarp();
        for (int j = 0; j < deg; j++) {
            int s = g_csr_src[base + j];
            float e = expf(g_elog[base + j] - mx);
            ssum += e;
            if (F == 256) {
                acc0 = f4_fma(e, v4[(size_t)s * 64 + lane], acc0);
                acc1 = f4_fma(e, v4[(size_t)s * 64 + 32 + lane], acc1);
            } else {
                acc0 = f4_fma(e, v4[(size_t)s * 32 + lane], acc0);
            }
        }
    }

    float inv = (deg > 0) ? 1.f / fmaxf(ssum, 1e-16f) : 0.f;
    if (F == 256) {
        size_t o = (size_t)n * 64;
        float4 rr = r4[o + lane], bb = b4[lane];
        h4[o + lane] = make_float4(acc0.x * inv + rr.x + bb.x, acc0.y * inv + rr.y + bb.y,
                                   acc0.z * inv + rr.z + bb.z, acc0.w * inv + rr.w + bb.w);
        rr = r4[o + 32 + lane]; bb = b4[32 + lane];
        h4[o + 32 + lane] = make_float4(acc1.x * inv + rr.x + bb.x, acc1.y * inv + rr.y + bb.y,
                                        acc1.z * inv + rr.z + bb.z, acc1.w * inv + rr.w + bb.w);
    } else {
        size_t o = (size_t)n * 32;
        float4 rr = r4[o + lane], bb = b4[lane];
        h4[o + lane] = make_float4(acc0.x * inv + rr.x + bb.x, acc0.y * inv + rr.y + bb.y,
                                   acc0.z * inv + rr.z + bb.z, acc0.w * inv + rr.w + bb.w);
    }
}

// ---------------- batch norm (double accumulation) ----------------
__global__ void bn_zero_kernel() {
    int f = threadIdx.x;
    g_sumd[f] = 0.0; g_sumsqd[f] = 0.0;
}
#define BN_ROWS 256
__global__ __launch_bounds__(256) void bn_stats_kernel(int F) {
    int r0 = blockIdx.x * BN_ROWS;
    int r1 = min(r0 + BN_ROWS, Nn);
    for (int f = threadIdx.x; f < F; f += 256) {
        double s = 0.0, q = 0.0;
        for (int r = r0; r < r1; r++) {
            float v = g_h[(size_t)r * F + f];
            s += (double)v; q += (double)v * (double)v;
        }
        atomicAdd(&g_sumd[f], s);
        atomicAdd(&g_sumsqd[f], q);
    }
}
__global__ void bn_finalize_kernel(int F) {
    int f = threadIdx.x;
    if (f < F) {
        double mu = g_sumd[f] / (double)Nn;
        double var = g_sumsqd[f] / (double)Nn - mu * mu;
        if (var < 0.0) var = 0.0;
        g_mean[f] = (float)mu;
        g_inv[f] = (float)(1.0 / sqrt(var + 1e-5));
    }
}
__global__ void bn_apply_relu_kernel(const float* __restrict__ gam,
                                     const float* __restrict__ bet, int F) {
    int i = blockIdx.x * blockDim.x + threadIdx.x;
    if (i < Nn * F) {
        int f = i % F;
        float v = (g_h[i] - g_mean[f]) * g_inv[f] * gam[f] + bet[f];
        g_x1[i] = v > 0.f ? v : 0.f;
    }
}
__global__ void final_out_kernel(const float* __restrict__ gam,
                                 const float* __restrict__ bet,
                                 const float* __restrict__ x0,
                                 float* __restrict__ out) {
    int i = blockIdx.x * blockDim.x + threadIdx.x;
    if (i < Nn * IOd) {
        int f = i % IOd;
        float v = (g_h[i] - g_mean[f]) * g_inv[f] * gam[f] + bet[f] + x0[i];
        out[i] = v > 0.f ? v : 0.f;
    }
}

// ---------------- launch sequence ----------------
extern "C" void kernel_launch(void* const* d_in, const int* in_sizes, int n_in,
                              void* d_out, int out_size) {
    const float* x0  = (const float*)d_in[0];
    const void*  edg = d_in[1];
    const float* Wq1 = (const float*)d_in[2];
    const float* Wk1 = (const float*)d_in[3];
    const float* Wv1 = (const float*)d_in[4];
    const float* Wr1 = (const float*)d_in[5];
    const float* b1  = (const float*)d_in[6];
    const float* g1  = (const float*)d_in[7];
    const float* be1 = (const float*)d_in[8];
    const float* Wq2 = (const float*)d_in[9];
    const float* Wk2 = (const float*)d_in[10];
    const float* Wv2 = (const float*)d_in[11];
    const float* Wr2 = (const float*)d_in[12];
    const float* b2  = (const float*)d_in[13];
    const float* g2  = (const float*)d_in[14];
    const float* be2 = (const float*)d_in[15];
    float* out = (float*)d_out;

    float *pq, *pk, *pv, *pr, *px1, *pwt;
    cudaGetSymbolAddress((void**)&pq,  g_q);
    cudaGetSymbolAddress((void**)&pk,  g_k);
    cudaGetSymbolAddress((void**)&pv,  g_v);
    cudaGetSymbolAddress((void**)&pr,  g_r);
    cudaGetSymbolAddress((void**)&px1, g_x1);
    cudaGetSymbolAddress((void**)&pwt, g_wt);

    const int SMEM_GEMM = 4 * 128 * SROW * 4;   // 73728 bytes
    cudaFuncSetAttribute(mma_gemm_kernel<128, 256>, cudaFuncAttributeMaxDynamicSharedMemorySize, SMEM_GEMM);
    cudaFuncSetAttribute(mma_gemm_kernel<256, 256>, cudaFuncAttributeMaxDynamicSharedMemorySize, SMEM_GEMM);
    cudaFuncSetAttribute(mma_gemm_kernel<256, 128>, cudaFuncAttributeMaxDynamicSharedMemorySize, SMEM_GEMM);

    const int EDGE_BLOCKS = (Ee + 255) / 256;
    const int NODE_BLOCKS = (Nn + 255) / 256;
    const int NH_BLOCKS = (Nn * HIDd + 255) / 256;
    const int NI_BLOCKS = (Nn * IOd + 255) / 256;
    const int BN_BLOCKS = (Nn + BN_ROWS - 1) / BN_ROWS;
    const int ATTN_BLOCKS = (Nn * 32 + 255) / 256;
    const int MB = (Nn + 127) / 128;   // 391
    dim3 g2d(MB, 2), g1d(MB, 1);

    detect_edges_kernel<<<1, 256>>>((const int*)edg);
    convert_edges_kernel<<<EDGE_BLOCKS, 256>>>(edg);

    csr_zero_kernel<<<NODE_BLOCKS, 256>>>();
    csr_count_kernel<<<EDGE_BLOCKS, 256>>>();
    scan1_kernel<<<NB_SCAN, 1024>>>();
    scan2_kernel<<<1, 1>>>();
    scan3_kernel<<<NB_SCAN, 1024>>>();
    csr_scatter_kernel<<<EDGE_BLOCKS, 256>>>();

    // transpose all 8 weight matrices into g_wt
    transpose_kernel<<<128, 256>>>(Wq1, pwt + WT_Q1, 128, 256);
    transpose_kernel<<<128, 256>>>(Wk1, pwt + WT_K1, 128, 256);
    transpose_kernel<<<128, 256>>>(Wv1, pwt + WT_V1, 128, 256);
    transpose_kernel<<<128, 256>>>(Wr1, pwt + WT_R1, 128, 256);
    transpose_kernel<<<256, 256>>>(Wq2, pwt + WT_Q2, 256, 256);
    transpose_kernel<<<256, 256>>>(Wk2, pwt + WT_K2, 256, 256);
    transpose_kernel<<<128, 256>>>(Wv2, pwt + WT_V2, 256, 128);
    transpose_kernel<<<128, 256>>>(Wr2, pwt + WT_R2, 256, 128);

    // ---- layer 1 (K=128, all outputs N=256) ----
    {
        mma_gemm_kernel<128, 256><<<g2d, 256, SMEM_GEMM>>>(x0, pwt + WT_Q1, pq, Nn);
        mma_gemm_kernel<128, 256><<<g2d, 256, SMEM_GEMM>>>(x0, pwt + WT_K1, pk, Nn);
        mma_gemm_kernel<128, 256><<<g2d, 256, SMEM_GEMM>>>(x0, pwt + WT_V1, pv, Nn);
        mma_gemm_kernel<128, 256><<<g2d, 256, SMEM_GEMM>>>(x0, pwt + WT_R1, pr, Nn);

        attn_kernel<256><<<ATTN_BLOCKS, 256>>>(b1);

        bn_zero_kernel<<<1, 256>>>();
        bn_stats_kernel<<<BN_BLOCKS, 256>>>(HIDd);
        bn_finalize_kernel<<<1, 256>>>(HIDd);
        bn_apply_relu_kernel<<<NH_BLOCKS, 256>>>(g1, be1, HIDd);
    }

    // ---- layer 2 (K=256; q,k N=256; v,r N=128) ----
    {
        mma_gemm_kernel<256, 256><<<g2d, 256, SMEM_GEMM>>>(px1, pwt + WT_Q2, pq, Nn);
        mma_gemm_kernel<256, 256><<<g2d, 256, SMEM_GEMM>>>(px1, pwt + WT_K2, pk, Nn);
        mma_gemm_kernel<256, 128><<<g1d, 256, SMEM_GEMM>>>(px1, pwt + WT_V2, pv, Nn);
        mma_gemm_kernel<256, 128><<<g1d, 256, SMEM_GEMM>>>(px1, pwt + WT_R2, pr, Nn);

        attn_kernel<128><<<ATTN_BLOCKS, 256>>>(b2);

        bn_zero_kernel<<<1, 256>>>();
        bn_stats_kernel<<<BN_BLOCKS, 256>>>(IOd);
        bn_finalize_kernel<<<1, 256>>>(IOd);
        final_out_kernel<<<NI_BLOCKS, 256>>>(g2, be2, x0, out);
    }
}

// round 6
// speedup vs baseline: 1.7513x; 1.0617x over previous
#include <cuda_runtime.h>
#include <cuda_fp16.h>
#include <math.h>
#include <stdint.h>

// Problem constants (fixed by the reference)
#define Nn   50000
#define Ee   800000
#define IOd  128
#define HIDd 256
#define KQd  256

// ---------------- device scratch (no allocations allowed) ----------------
__device__ __half g_qh[Nn * KQd];
__device__ __half g_kh[Nn * KQd];
__device__ float g_v[Nn * HIDd];
__device__ float g_r[Nn * HIDd];
__device__ float g_h[Nn * HIDd];
__device__ float g_x1[Nn * HIDd];
__device__ float g_elog[Ee];
__device__ float g_wt[327680];      // transposed weights
__device__ int   g_src[Ee];
__device__ int   g_dst[Ee];
__device__ int   g_csr_src[Ee];
__device__ int   g_deg[Nn];
__device__ int   g_inc[Nn];
__device__ int   g_fill[Nn];
#define NB_SCAN 49
__device__ int   g_bsum[NB_SCAN];
__device__ int   g_boff[NB_SCAN];
__device__ double g_sumd[HIDd];
__device__ double g_sumsqd[HIDd];
__device__ float g_mean[HIDd];
__device__ float g_inv[HIDd];
__device__ int   g_flag64[1];

// transposed-weight offsets in g_wt
#define WT_Q1 0
#define WT_K1 32768
#define WT_V1 65536
#define WT_R1 98304
#define WT_Q2 131072
#define WT_K2 196608
#define WT_V2 262144
#define WT_R2 294912

// ---------------- helpers ----------------
__device__ __forceinline__ uint32_t smem_u32(const void* p) {
    uint32_t a;
    asm("{ .reg .u64 t; cvta.to.shared.u64 t, %1; cvt.u32.u64 %0, t; }" : "=r"(a) : "l"(p));
    return a;
}
__device__ __forceinline__ void cp_async16(uint32_t sm, const void* g) {
    asm volatile("cp.async.cg.shared.global [%0], [%1], 16;" :: "r"(sm), "l"(g));
}
__device__ __forceinline__ void cp_commit() { asm volatile("cp.async.commit_group;"); }
__device__ __forceinline__ void cp_wait1() { asm volatile("cp.async.wait_group 1;"); }
__device__ __forceinline__ void cp_wait0() { asm volatile("cp.async.wait_group 0;"); }

// ---------------- weight transpose: Wt[n*K+k] = W[k*N+n] ----------------
__global__ void transpose_kernel(const float* __restrict__ W, float* __restrict__ Wt,
                                 int K, int N) {
    int i = blockIdx.x * 256 + threadIdx.x;
    if (i < K * N) {
        int k = i / N, n = i % N;
        Wt[n * K + k] = W[i];
    }
}

// ---------------- HMMA tf32 GEMM: C[M,N] = A[M,K] @ Bt[N,K]^T --------------
// CTA tile 128x128, 8 warps (2 M x 4 N), warp tile 64x32.
#define SROW 36

template <int K, int N, typename OutT>
__global__ __launch_bounds__(256) void mma_gemm_kernel(
    const float* __restrict__ A, const float* __restrict__ Bt,
    OutT* __restrict__ C, int M)
{
    extern __shared__ float smem[];
    float* As = smem;                    // 2 x 128 x SROW
    float* Bs = smem + 2 * 128 * SROW;   // 2 x 128 x SROW

    const int tid = threadIdx.x;
    const int wid = tid >> 5;
    const int lane = tid & 31;
    const int gID = lane >> 2;
    const int tig = lane & 3;
    const int wm = (wid & 1) * 64;
    const int wn = (wid >> 1) * 32;
    const int m0 = blockIdx.x * 128;
    const int n0 = blockIdx.y * 128;

    float c[4][4][4] = {};

    constexpr int NC = K / 32;

    auto stage = [&](int cc, int buf) {
        const int k0 = cc * 32;
        float* ab = As + buf * (128 * SROW);
        float* bb = Bs + buf * (128 * SROW);
        #pragma unroll
        for (int i = 0; i < 4; i++) {
            int idx = tid + i * 256;
            int row = idx >> 3, g = idx & 7;
            int gr = m0 + row; if (gr >= M) gr = M - 1;
            cp_async16(smem_u32(ab + row * SROW + g * 4), A + (size_t)gr * K + k0 + g * 4);
        }
        #pragma unroll
        for (int i = 0; i < 4; i++) {
            int idx = tid + i * 256;
            int row = idx >> 3, g = idx & 7;
            cp_async16(smem_u32(bb + row * SROW + g * 4), Bt + (size_t)(n0 + row) * K + k0 + g * 4);
        }
        cp_commit();
    };

    stage(0, 0);
    for (int cc = 0; cc < NC; cc++) {
        const int buf = cc & 1;
        if (cc + 1 < NC) { stage(cc + 1, buf ^ 1); cp_wait1(); }
        else             { cp_wait0(); }
        __syncthreads();

        const float* ab = As + buf * (128 * SROW);
        const float* bb = Bs + buf * (128 * SROW);

        #pragma unroll
        for (int ks = 0; ks < 4; ks++) {
            const int kk = ks * 8;
            uint32_t af[4][4];
            #pragma unroll
            for (int mf = 0; mf < 4; mf++) {
                const float* base = ab + (wm + mf * 16) * SROW + kk;
                af[mf][0] = __float_as_uint(base[gID * SROW + tig]);
                af[mf][1] = __float_as_uint(base[(gID + 8) * SROW + tig]);
                af[mf][2] = __float_as_uint(base[gID * SROW + tig + 4]);
                af[mf][3] = __float_as_uint(base[(gID + 8) * SROW + tig + 4]);
            }
            uint32_t bf[4][2];
            #pragma unroll
            for (int nf = 0; nf < 4; nf++) {
                const float* base = bb + (wn + nf * 8 + gID) * SROW + kk;
                bf[nf][0] = __float_as_uint(base[tig]);
                bf[nf][1] = __float_as_uint(base[tig + 4]);
            }
            #pragma unroll
            for (int mf = 0; mf < 4; mf++)
                #pragma unroll
                for (int nf = 0; nf < 4; nf++)
                    asm volatile(
                        "mma.sync.aligned.m16n8k8.row.col.f32.tf32.tf32.f32 "
                        "{%0,%1,%2,%3}, {%4,%5,%6,%7}, {%8,%9}, {%0,%1,%2,%3};"
                        : "+f"(c[mf][nf][0]), "+f"(c[mf][nf][1]),
                          "+f"(c[mf][nf][2]), "+f"(c[mf][nf][3])
                        : "r"(af[mf][0]), "r"(af[mf][1]), "r"(af[mf][2]), "r"(af[mf][3]),
                          "r"(bf[nf][0]), "r"(bf[nf][1]));
        }
        __syncthreads();
    }

    #pragma unroll
    for (int mf = 0; mf < 4; mf++) {
        int row = m0 + wm + mf * 16 + gID;
        #pragma unroll
        for (int nf = 0; nf < 4; nf++) {
            int col = n0 + wn + nf * 8 + tig * 2;
            if (row < M) {
                if constexpr (sizeof(OutT) == 2)
                    *(__half2*)(C + (size_t)row * N + col) = __floats2half2_rn(c[mf][nf][0], c[mf][nf][1]);
                else
                    *(float2*)(C + (size_t)row * N + col) = make_float2(c[mf][nf][0], c[mf][nf][1]);
            }
            if (row + 8 < M) {
                if constexpr (sizeof(OutT) == 2)
                    *(__half2*)(C + (size_t)(row + 8) * N + col) = __floats2half2_rn(c[mf][nf][2], c[mf][nf][3]);
                else
                    *(float2*)(C + (size_t)(row + 8) * N + col) = make_float2(c[mf][nf][2], c[mf][nf][3]);
            }
        }
    }
}

// ---------------- edge dtype detection + conversion ----------------
__global__ void detect_edges_kernel(const int* __restrict__ ew) {
    __shared__ int nz;
    if (threadIdx.x == 0) nz = 0;
    __syncthreads();
    int stride = Ee / 256;
    int idx = 2 * (threadIdx.x * stride) + 1;
    if (ew[idx] != 0) atomicOr(&nz, 1);
    __syncthreads();
    if (threadIdx.x == 0) g_flag64[0] = nz ? 0 : 1;
}

__global__ void convert_edges_kernel(const void* __restrict__ edges) {
    int e = blockIdx.x * blockDim.x + threadIdx.x;
    if (e >= Ee) return;
    if (g_flag64[0]) {
        const long long* p = (const long long*)edges;
        g_src[e] = (int)p[e];
        g_dst[e] = (int)p[Ee + e];
    } else {
        const int* p = (const int*)edges;
        g_src[e] = p[e];
        g_dst[e] = p[Ee + e];
    }
}

// ---------------- CSR build ----------------
__global__ void csr_zero_kernel() {
    int i = blockIdx.x * blockDim.x + threadIdx.x;
    if (i < Nn) { g_deg[i] = 0; g_fill[i] = 0; }
}
__global__ void csr_count_kernel() {
    int e = blockIdx.x * blockDim.x + threadIdx.x;
    if (e < Ee) atomicAdd(&g_deg[g_dst[e]], 1);
}
__global__ void scan1_kernel() {
    __shared__ int sm[1024];
    int i = blockIdx.x * 1024 + threadIdx.x;
    int v = (i < Nn) ? g_deg[i] : 0;
    sm[threadIdx.x] = v;
    __syncthreads();
    for (int off = 1; off < 1024; off <<= 1) {
        int t = (threadIdx.x >= off) ? sm[threadIdx.x - off] : 0;
        __syncthreads();
        sm[threadIdx.x] += t;
        __syncthreads();
    }
    if (i < Nn) g_inc[i] = sm[threadIdx.x];
    if (threadIdx.x == 1023) g_bsum[blockIdx.x] = sm[1023];
}
__global__ void scan2_kernel() {
    int acc = 0;
    for (int b = 0; b < NB_SCAN; b++) { g_boff[b] = acc; acc += g_bsum[b]; }
}
__global__ void scan3_kernel() {
    int i = blockIdx.x * 1024 + threadIdx.x;
    if (i < Nn) g_inc[i] += g_boff[blockIdx.x];
}
__global__ void csr_scatter_kernel() {
    int e = blockIdx.x * blockDim.x + threadIdx.x;
    if (e >= Ee) return;
    int d = g_dst[e];
    int pos = g_inc[d] - g_deg[d] + atomicAdd(&g_fill[d], 1);
    g_csr_src[pos] = g_src[e];
}

// ---------------- warp-per-node attention + aggregation ----------------
// q,k stored fp16 (logits only); v,r fp32.
__device__ __forceinline__ float4 f4_fma(float s, float4 a, float4 acc) {
    acc.x += s * a.x; acc.y += s * a.y; acc.z += s * a.z; acc.w += s * a.w;
    return acc;
}
__device__ __forceinline__ float dot8h(uint4 a, uint4 b) {
    const __half2* ah = (const __half2*)&a;
    const __half2* bh = (const __half2*)&b;
    float p = 0.f;
    #pragma unroll
    for (int i = 0; i < 4; i++) {
        float2 fa = __half22float2(ah[i]);
        float2 fb = __half22float2(bh[i]);
        p += fa.x * fb.x + fa.y * fb.y;
    }
    return p;
}

template <int F>
__global__ __launch_bounds__(256) void attn_kernel(const float* __restrict__ bias) {
    int n = (blockIdx.x * blockDim.x + threadIdx.x) >> 5;
    int lane = threadIdx.x & 31;
    if (n >= Nn) return;

    int deg = g_deg[n];
    int base = g_inc[n] - deg;

    const uint4* qh = (const uint4*)g_qh;   // 32 uint4 per row (256 halves)
    const uint4* kh = (const uint4*)g_kh;
    const float4* v4 = (const float4*)g_v;
    const float4* r4 = (const float4*)g_r;
    const float4* b4 = (const float4*)bias;
    float4* h4 = (float4*)g_h;

    float4 acc0 = make_float4(0.f, 0.f, 0.f, 0.f);
    float4 acc1 = make_float4(0.f, 0.f, 0.f, 0.f);
    float ssum = 0.f;

    if (deg > 0) {
        uint4 qreg = qh[(size_t)n * 32 + lane];
        float mx = -INFINITY;
        for (int j = 0; j < deg; j++) {
            int s = g_csr_src[base + j];
            float p = dot8h(qreg, kh[(size_t)s * 32 + lane]);
            #pragma unroll
            for (int off = 16; off; off >>= 1)
                p += __shfl_xor_sync(0xffffffffu, p, off);
            p *= 0.0625f;
            if (lane == 0) g_elog[base + j] = p;
            mx = fmaxf(mx, p);
        }
        __syncwarp();
        for (int j = 0; j < deg; j++) {
            int s = g_csr_src[base + j];
            float e = expf(g_elog[base + j] - mx);
            ssum += e;
            if (F == 256) {
                acc0 = f4_fma(e, v4[(size_t)s * 64 + lane], acc0);
                acc1 = f4_fma(e, v4[(size_t)s * 64 + 32 + lane], acc1);
            } else {
                acc0 = f4_fma(e, v4[(size_t)s * 32 + lane], acc0);
            }
        }
    }

    float inv = (deg > 0) ? 1.f / fmaxf(ssum, 1e-16f) : 0.f;
    if (F == 256) {
        size_t o = (size_t)n * 64;
        float4 rr = r4[o + lane], bb = b4[lane];
        h4[o + lane] = make_float4(acc0.x * inv + rr.x + bb.x, acc0.y * inv + rr.y + bb.y,
                                   acc0.z * inv + rr.z + bb.z, acc0.w * inv + rr.w + bb.w);
        rr = r4[o + 32 + lane]; bb = b4[32 + lane];
        h4[o + 32 + lane] = make_float4(acc1.x * inv + rr.x + bb.x, acc1.y * inv + rr.y + bb.y,
                                        acc1.z * inv + rr.z + bb.z, acc1.w * inv + rr.w + bb.w);
    } else {
        size_t o = (size_t)n * 32;
        float4 rr = r4[o + lane], bb = b4[lane];
        h4[o + lane] = make_float4(acc0.x * inv + rr.x + bb.x, acc0.y * inv + rr.y + bb.y,
                                   acc0.z * inv + rr.z + bb.z, acc0.w * inv + rr.w + bb.w);
    }
}

// ---------------- batch norm (double accumulation) ----------------
__global__ void bn_zero_kernel() {
    int f = threadIdx.x;
    g_sumd[f] = 0.0; g_sumsqd[f] = 0.0;
}
#define BN_ROWS 256
__global__ __launch_bounds__(256) void bn_stats_kernel(int F) {
    int r0 = blockIdx.x * BN_ROWS;
    int r1 = min(r0 + BN_ROWS, Nn);
    for (int f = threadIdx.x; f < F; f += 256) {
        double s = 0.0, q = 0.0;
        for (int r = r0; r < r1; r++) {
            float v = g_h[(size_t)r * F + f];
            s += (double)v; q += (double)v * (double)v;
        }
        atomicAdd(&g_sumd[f], s);
        atomicAdd(&g_sumsqd[f], q);
    }
}
__global__ void bn_finalize_kernel(int F) {
    int f = threadIdx.x;
    if (f < F) {
        double mu = g_sumd[f] / (double)Nn;
        double var = g_sumsqd[f] / (double)Nn - mu * mu;
        if (var < 0.0) var = 0.0;
        g_mean[f] = (float)mu;
        g_inv[f] = (float)(1.0 / sqrt(var + 1e-5));
    }
}
__global__ void bn_apply_relu_kernel(const float* __restrict__ gam,
                                     const float* __restrict__ bet, int F) {
    int i = blockIdx.x * blockDim.x + threadIdx.x;
    if (i < Nn * F) {
        int f = i % F;
        float v = (g_h[i] - g_mean[f]) * g_inv[f] * gam[f] + bet[f];
        g_x1[i] = v > 0.f ? v : 0.f;
    }
}
__global__ void final_out_kernel(const float* __restrict__ gam,
                                 const float* __restrict__ bet,
                                 const float* __restrict__ x0,
                                 float* __restrict__ out) {
    int i = blockIdx.x * blockDim.x + threadIdx.x;
    if (i < Nn * IOd) {
        int f = i % IOd;
        float v = (g_h[i] - g_mean[f]) * g_inv[f] * gam[f] + bet[f] + x0[i];
        out[i] = v > 0.f ? v : 0.f;
    }
}

// ---------------- launch sequence ----------------
extern "C" void kernel_launch(void* const* d_in, const int* in_sizes, int n_in,
                              void* d_out, int out_size) {
    const float* x0  = (const float*)d_in[0];
    const void*  edg = d_in[1];
    const float* Wq1 = (const float*)d_in[2];
    const float* Wk1 = (const float*)d_in[3];
    const float* Wv1 = (const float*)d_in[4];
    const float* Wr1 = (const float*)d_in[5];
    const float* b1  = (const float*)d_in[6];
    const float* g1  = (const float*)d_in[7];
    const float* be1 = (const float*)d_in[8];
    const float* Wq2 = (const float*)d_in[9];
    const float* Wk2 = (const float*)d_in[10];
    const float* Wv2 = (const float*)d_in[11];
    const float* Wr2 = (const float*)d_in[12];
    const float* b2  = (const float*)d_in[13];
    const float* g2  = (const float*)d_in[14];
    const float* be2 = (const float*)d_in[15];
    float* out = (float*)d_out;

    __half *pqh, *pkh;
    float *pv, *pr, *px1, *pwt;
    cudaGetSymbolAddress((void**)&pqh, g_qh);
    cudaGetSymbolAddress((void**)&pkh, g_kh);
    cudaGetSymbolAddress((void**)&pv,  g_v);
    cudaGetSymbolAddress((void**)&pr,  g_r);
    cudaGetSymbolAddress((void**)&px1, g_x1);
    cudaGetSymbolAddress((void**)&pwt, g_wt);

    const int SMEM_GEMM = 4 * 128 * SROW * 4;   // 73728 bytes
    cudaFuncSetAttribute((const void*)mma_gemm_kernel<128, 256, __half>, cudaFuncAttributeMaxDynamicSharedMemorySize, SMEM_GEMM);
    cudaFuncSetAttribute((const void*)mma_gemm_kernel<128, 256, float>,  cudaFuncAttributeMaxDynamicSharedMemorySize, SMEM_GEMM);
    cudaFuncSetAttribute((const void*)mma_gemm_kernel<256, 256, __half>, cudaFuncAttributeMaxDynamicSharedMemorySize, SMEM_GEMM);
    cudaFuncSetAttribute((const void*)mma_gemm_kernel<256, 128, float>,  cudaFuncAttributeMaxDynamicSharedMemorySize, SMEM_GEMM);

    const int EDGE_BLOCKS = (Ee + 255) / 256;
    const int NODE_BLOCKS = (Nn + 255) / 256;
    const int NH_BLOCKS = (Nn * HIDd + 255) / 256;
    const int NI_BLOCKS = (Nn * IOd + 255) / 256;
    const int BN_BLOCKS = (Nn + BN_ROWS - 1) / BN_ROWS;
    const int ATTN_BLOCKS = (Nn * 32 + 255) / 256;
    const int MB = (Nn + 127) / 128;   // 391
    dim3 g2d(MB, 2), g1d(MB, 1);

    detect_edges_kernel<<<1, 256>>>((const int*)edg);
    convert_edges_kernel<<<EDGE_BLOCKS, 256>>>(edg);

    csr_zero_kernel<<<NODE_BLOCKS, 256>>>();
    csr_count_kernel<<<EDGE_BLOCKS, 256>>>();
    scan1_kernel<<<NB_SCAN, 1024>>>();
    scan2_kernel<<<1, 1>>>();
    scan3_kernel<<<NB_SCAN, 1024>>>();
    csr_scatter_kernel<<<EDGE_BLOCKS, 256>>>();

    transpose_kernel<<<128, 256>>>(Wq1, pwt + WT_Q1, 128, 256);
    transpose_kernel<<<128, 256>>>(Wk1, pwt + WT_K1, 128, 256);
    transpose_kernel<<<128, 256>>>(Wv1, pwt + WT_V1, 128, 256);
    transpose_kernel<<<128, 256>>>(Wr1, pwt + WT_R1, 128, 256);
    transpose_kernel<<<256, 256>>>(Wq2, pwt + WT_Q2, 256, 256);
    transpose_kernel<<<256, 256>>>(Wk2, pwt + WT_K2, 256, 256);
    transpose_kernel<<<128, 256>>>(Wv2, pwt + WT_V2, 256, 128);
    transpose_kernel<<<128, 256>>>(Wr2, pwt + WT_R2, 256, 128);

    // ---- layer 1 (K=128) ----
    {
        mma_gemm_kernel<128, 256, __half><<<g2d, 256, SMEM_GEMM>>>(x0, pwt + WT_Q1, pqh, Nn);
        mma_gemm_kernel<128, 256, __half><<<g2d, 256, SMEM_GEMM>>>(x0, pwt + WT_K1, pkh, Nn);
        mma_gemm_kernel<128, 256, float><<<g2d, 256, SMEM_GEMM>>>(x0, pwt + WT_V1, pv, Nn);
        mma_gemm_kernel<128, 256, float><<<g2d, 256, SMEM_GEMM>>>(x0, pwt + WT_R1, pr, Nn);

        attn_kernel<256><<<ATTN_BLOCKS, 256>>>(b1);

        bn_zero_kernel<<<1, 256>>>();
        bn_stats_kernel<<<BN_BLOCKS, 256>>>(HIDd);
        bn_finalize_kernel<<<1, 256>>>(HIDd);
        bn_apply_relu_kernel<<<NH_BLOCKS, 256>>>(g1, be1, HIDd);
    }

    // ---- layer 2 (K=256; q,k N=256; v,r N=128) ----
    {
        mma_gemm_kernel<256, 256, __half><<<g2d, 256, SMEM_GEMM>>>(px1, pwt + WT_Q2, pqh, Nn);
        mma_gemm_kernel<256, 256, __half><<<g2d, 256, SMEM_GEMM>>>(px1, pwt + WT_K2, pkh, Nn);
        mma_gemm_kernel<256, 128, float><<<g1d, 256, SMEM_GEMM>>>(px1, pwt + WT_V2, pv, Nn);
        mma_gemm_kernel<256, 128, float><<<g1d, 256, SMEM_GEMM>>>(px1, pwt + WT_R2, pr, Nn);

        attn_kernel<128><<<ATTN_BLOCKS, 256>>>(b2);

        bn_zero_kernel<<<1, 256>>>();
        bn_stats_kernel<<<BN_BLOCKS, 256>>>(IOd);
        bn_finalize_kernel<<<1, 256>>>(IOd);
        final_out_kernel<<<NI_BLOCKS, 256>>>(g2, be2, x0, out);
    }
}

// round 7
// speedup vs baseline: 1.8998x; 1.0848x over previous
#include <cuda_runtime.h>
#include <cuda_fp16.h>
#include <math.h>
#include <stdint.h>

// Problem constants (fixed by the reference)
#define Nn   50000
#define Ee   800000
#define IOd  128
#define HIDd 256
#define KQd  256

// ---------------- device scratch (no allocations allowed) ----------------
__device__ __half g_qh[Nn * KQd];
__device__ __half g_kh[Nn * KQd];
__device__ float g_v[Nn * HIDd];
__device__ float g_r[Nn * HIDd];
__device__ float g_h[Nn * HIDd];
__device__ float g_x1[Nn * HIDd];
__device__ float g_wt[327680];      // transposed weights (concatenated per layer)
__device__ int   g_src[Ee];
__device__ int   g_dst[Ee];
__device__ int   g_csr_src[Ee];
__device__ int   g_deg[Nn];
__device__ int   g_inc[Nn];
__device__ int   g_fill[Nn];
#define NB_SCAN 49
__device__ int   g_bsum[NB_SCAN];
__device__ int   g_boff[NB_SCAN];
__device__ double g_sumd[HIDd];     // zero at call entry; finalize re-zeros
__device__ double g_sumsqd[HIDd];
__device__ float g_mean[HIDd];
__device__ float g_inv[HIDd];
__device__ int   g_flag64[1];

// transposed-weight offsets in g_wt (layer1 block contiguous, then layer2)
#define WT_L1 0         // [1024 x 128]: Q1,K1,V1,R1
#define WT_L2 131072    // [768 x 256]:  Q2,K2,V2,R2

// ---------------- helpers ----------------
__device__ __forceinline__ uint32_t smem_u32(const void* p) {
    uint32_t a;
    asm("{ .reg .u64 t; cvta.to.shared.u64 t, %1; cvt.u32.u64 %0, t; }" : "=r"(a) : "l"(p));
    return a;
}
__device__ __forceinline__ void cp_async16(uint32_t sm, const void* g) {
    asm volatile("cp.async.cg.shared.global [%0], [%1], 16;" :: "r"(sm), "l"(g));
}
__device__ __forceinline__ void cp_commit() { asm volatile("cp.async.commit_group;"); }
__device__ __forceinline__ void cp_wait1() { asm volatile("cp.async.wait_group 1;"); }
__device__ __forceinline__ void cp_wait0() { asm volatile("cp.async.wait_group 0;"); }

// ---------------- all-weights transpose (one launch) ----------------
struct W8 { const float* w[8]; };
// segments: 4 x (K=128,N=256,sz=32768), 2 x (K=256,N=256,sz=65536), 2 x (K=256,N=128,sz=32768)
__global__ void transpose_all_kernel(W8 ws, float* __restrict__ Wt) {
    int i = blockIdx.x * 256 + threadIdx.x;
    if (i >= 327680) return;
    int seg, base, K, N, dst;
    if (i < 131072)      { seg = i >> 15;       base = seg << 15;          K = 128; N = 256; dst = seg * 32768; }
    else if (i < 262144) { seg = 4 + ((i - 131072) >> 16); base = 131072 + ((seg - 4) << 16); K = 256; N = 256; dst = 131072 + (seg - 4) * 65536; }
    else                 { seg = 6 + ((i - 262144) >> 15); base = 262144 + ((seg - 6) << 15); K = 256; N = 128; dst = 262144 + (seg - 6) * 32768; }
    int il = i - base;
    int k = il / N, n = il % N;
    Wt[dst + n * K + k] = ws.w[seg][il];
}

// ---------------- fused HMMA tf32 GEMM (4 outputs per layer) ----------------
// CTA tile 128x128, 8 warps (2 M x 4 N), warp tile 64x32, mma.m16n8k8.
#define SROW 36

template <int LAYER>
__global__ __launch_bounds__(256) void fused_gemm_kernel(
    const float* __restrict__ A, const float* __restrict__ BtAll,
    __half* __restrict__ Oq, __half* __restrict__ Ok,
    float* __restrict__ Ov, float* __restrict__ Or, int M)
{
    constexpr int K = (LAYER == 1) ? 128 : 256;
    extern __shared__ float smem[];
    float* As = smem;                    // 2 x 128 x SROW
    float* Bs = smem + 2 * 128 * SROW;

    const int tid = threadIdx.x;
    const int wid = tid >> 5;
    const int lane = tid & 31;
    const int gID = lane >> 2;
    const int tig = lane & 3;
    const int wm = (wid & 1) * 64;
    const int wn = (wid >> 1) * 32;
    const int m0 = blockIdx.x * 128;
    const int y = blockIdx.y;
    const int nb0 = y * 128;             // row offset into BtAll

    float c[4][4][4] = {};
    constexpr int NC = K / 32;

    auto stage = [&](int cc, int buf) {
        const int k0 = cc * 32;
        float* ab = As + buf * (128 * SROW);
        float* bb = Bs + buf * (128 * SROW);
        #pragma unroll
        for (int i = 0; i < 4; i++) {
            int idx = tid + i * 256;
            int row = idx >> 3, g = idx & 7;
            int gr = m0 + row; if (gr >= M) gr = M - 1;
            cp_async16(smem_u32(ab + row * SROW + g * 4), A + (size_t)gr * K + k0 + g * 4);
        }
        #pragma unroll
        for (int i = 0; i < 4; i++) {
            int idx = tid + i * 256;
            int row = idx >> 3, g = idx & 7;
            cp_async16(smem_u32(bb + row * SROW + g * 4), BtAll + (size_t)(nb0 + row) * K + k0 + g * 4);
        }
        cp_commit();
    };

    stage(0, 0);
    for (int cc = 0; cc < NC; cc++) {
        const int buf = cc & 1;
        if (cc + 1 < NC) { stage(cc + 1, buf ^ 1); cp_wait1(); }
        else             { cp_wait0(); }
        __syncthreads();

        const float* ab = As + buf * (128 * SROW);
        const float* bb = Bs + buf * (128 * SROW);

        #pragma unroll
        for (int ks = 0; ks < 4; ks++) {
            const int kk = ks * 8;
            uint32_t af[4][4];
            #pragma unroll
            for (int mf = 0; mf < 4; mf++) {
                const float* base = ab + (wm + mf * 16) * SROW + kk;
                af[mf][0] = __float_as_uint(base[gID * SROW + tig]);
                af[mf][1] = __float_as_uint(base[(gID + 8) * SROW + tig]);
                af[mf][2] = __float_as_uint(base[gID * SROW + tig + 4]);
                af[mf][3] = __float_as_uint(base[(gID + 8) * SROW + tig + 4]);
            }
            uint32_t bf[4][2];
            #pragma unroll
            for (int nf = 0; nf < 4; nf++) {
                const float* base = bb + (wn + nf * 8 + gID) * SROW + kk;
                bf[nf][0] = __float_as_uint(base[tig]);
                bf[nf][1] = __float_as_uint(base[tig + 4]);
            }
            #pragma unroll
            for (int mf = 0; mf < 4; mf++)
                #pragma unroll
                for (int nf = 0; nf < 4; nf++)
                    asm volatile(
                        "mma.sync.aligned.m16n8k8.row.col.f32.tf32.tf32.f32 "
                        "{%0,%1,%2,%3}, {%4,%5,%6,%7}, {%8,%9}, {%0,%1,%2,%3};"
                        : "+f"(c[mf][nf][0]), "+f"(c[mf][nf][1]),
                          "+f"(c[mf][nf][2]), "+f"(c[mf][nf][3])
                        : "r"(af[mf][0]), "r"(af[mf][1]), "r"(af[mf][2]), "r"(af[mf][3]),
                          "r"(bf[nf][0]), "r"(bf[nf][1]));
        }
        __syncthreads();
    }

    // output routing
    __half* hout = nullptr; float* fout = nullptr;
    int Nout, cb;
    if (LAYER == 1) {
        int oi = y >> 1; cb = (y & 1) * 128; Nout = 256;
        if (oi == 0) hout = Oq; else if (oi == 1) hout = Ok;
        else if (oi == 2) fout = Ov; else fout = Or;
    } else {
        if (y < 4) { int oi = y >> 1; cb = (y & 1) * 128; Nout = 256; hout = (oi == 0) ? Oq : Ok; }
        else       { cb = 0; Nout = 128; fout = (y == 4) ? Ov : Or; }
    }

    #pragma unroll
    for (int mf = 0; mf < 4; mf++) {
        int row = m0 + wm + mf * 16 + gID;
        #pragma unroll
        for (int nf = 0; nf < 4; nf++) {
            int col = cb + wn + nf * 8 + tig * 2;
            if (hout) {
                if (row < M)
                    *(__half2*)(hout + (size_t)row * Nout + col) = __floats2half2_rn(c[mf][nf][0], c[mf][nf][1]);
                if (row + 8 < M)
                    *(__half2*)(hout + (size_t)(row + 8) * Nout + col) = __floats2half2_rn(c[mf][nf][2], c[mf][nf][3]);
            } else {
                if (row < M)
                    *(float2*)(fout + (size_t)row * Nout + col) = make_float2(c[mf][nf][0], c[mf][nf][1]);
                if (row + 8 < M)
                    *(float2*)(fout + (size_t)(row + 8) * Nout + col) = make_float2(c[mf][nf][2], c[mf][nf][3]);
            }
        }
    }
}

// ---------------- setup: zero + edge dtype detect ----------------
__global__ void detect_zero_kernel(const int* __restrict__ ew) {
    int i = blockIdx.x * blockDim.x + threadIdx.x;
    if (i < Nn) { g_deg[i] = 0; g_fill[i] = 0; }
    if (blockIdx.x == 0) {
        __shared__ int nz;
        if (threadIdx.x == 0) nz = 0;
        __syncthreads();
        int stride = Ee / 256;
        int idx = 2 * (threadIdx.x * stride) + 1;
        if (ew[idx] != 0) atomicOr(&nz, 1);
        __syncthreads();
        if (threadIdx.x == 0) g_flag64[0] = nz ? 0 : 1;
    }
}

// convert edges + count degrees in one pass
__global__ void convert_count_kernel(const void* __restrict__ edges) {
    int e = blockIdx.x * blockDim.x + threadIdx.x;
    if (e >= Ee) return;
    int s, d;
    if (g_flag64[0]) {
        const long long* p = (const long long*)edges;
        s = (int)p[e]; d = (int)p[Ee + e];
    } else {
        const int* p = (const int*)edges;
        s = p[e]; d = p[Ee + e];
    }
    g_src[e] = s; g_dst[e] = d;
    atomicAdd(&g_deg[d], 1);
}

// ---------------- CSR scan + scatter ----------------
__global__ void scan1_kernel() {
    __shared__ int sm[1024];
    int i = blockIdx.x * 1024 + threadIdx.x;
    int v = (i < Nn) ? g_deg[i] : 0;
    sm[threadIdx.x] = v;
    __syncthreads();
    for (int off = 1; off < 1024; off <<= 1) {
        int t = (threadIdx.x >= off) ? sm[threadIdx.x - off] : 0;
        __syncthreads();
        sm[threadIdx.x] += t;
        __syncthreads();
    }
    if (i < Nn) g_inc[i] = sm[threadIdx.x];
    if (threadIdx.x == 1023) g_bsum[blockIdx.x] = sm[1023];
}
__global__ void scan2_kernel() {
    int acc = 0;
    for (int b = 0; b < NB_SCAN; b++) { g_boff[b] = acc; acc += g_bsum[b]; }
}
__global__ void scan3_kernel() {
    int i = blockIdx.x * 1024 + threadIdx.x;
    if (i < Nn) g_inc[i] += g_boff[blockIdx.x];
}
__global__ void csr_scatter_kernel() {
    int e = blockIdx.x * blockDim.x + threadIdx.x;
    if (e >= Ee) return;
    int d = g_dst[e];
    int pos = g_inc[d] - g_deg[d] + atomicAdd(&g_fill[d], 1);
    g_csr_src[pos] = g_src[e];
}

// ---------------- warp-per-node attention, online softmax (one pass) -------
__device__ __forceinline__ float dot8h(uint4 a, uint4 b) {
    const __half2* ah = (const __half2*)&a;
    const __half2* bh = (const __half2*)&b;
    float p = 0.f;
    #pragma unroll
    for (int i = 0; i < 4; i++) {
        float2 fa = __half22float2(ah[i]);
        float2 fb = __half22float2(bh[i]);
        p += fa.x * fb.x + fa.y * fb.y;
    }
    return p;
}

template <int F>
__global__ __launch_bounds__(256) void attn_kernel(const float* __restrict__ bias) {
    int n = (blockIdx.x * blockDim.x + threadIdx.x) >> 5;
    int lane = threadIdx.x & 31;
    if (n >= Nn) return;

    int deg = g_deg[n];
    int base = g_inc[n] - deg;

    const uint4* qh = (const uint4*)g_qh;
    const uint4* kh = (const uint4*)g_kh;
    const float4* v4 = (const float4*)g_v;
    const float4* r4 = (const float4*)g_r;
    const float4* b4 = (const float4*)bias;
    float4* h4 = (float4*)g_h;

    float4 acc0 = make_float4(0.f, 0.f, 0.f, 0.f);
    float4 acc1 = make_float4(0.f, 0.f, 0.f, 0.f);
    float ssum = 0.f;

    if (deg > 0) {
        uint4 qreg = qh[(size_t)n * 32 + lane];
        float mx = -INFINITY;
        for (int j = 0; j < deg; j++) {
            int s = g_csr_src[base + j];
            float p = dot8h(qreg, kh[(size_t)s * 32 + lane]);
            #pragma unroll
            for (int off = 16; off; off >>= 1)
                p += __shfl_xor_sync(0xffffffffu, p, off);
            p *= 0.0625f;
            float mnew = fmaxf(mx, p);
            float corr = expf(mx - mnew);   // 0 on first iter (mx = -inf)
            float e = expf(p - mnew);
            ssum = ssum * corr + e;
            if (F == 256) {
                float4 va = v4[(size_t)s * 64 + lane];
                float4 vb = v4[(size_t)s * 64 + 32 + lane];
                acc0.x = acc0.x * corr + e * va.x; acc0.y = acc0.y * corr + e * va.y;
                acc0.z = acc0.z * corr + e * va.z; acc0.w = acc0.w * corr + e * va.w;
                acc1.x = acc1.x * corr + e * vb.x; acc1.y = acc1.y * corr + e * vb.y;
                acc1.z = acc1.z * corr + e * vb.z; acc1.w = acc1.w * corr + e * vb.w;
            } else {
                float4 va = v4[(size_t)s * 32 + lane];
                acc0.x = acc0.x * corr + e * va.x; acc0.y = acc0.y * corr + e * va.y;
                acc0.z = acc0.z * corr + e * va.z; acc0.w = acc0.w * corr + e * va.w;
            }
            mx = mnew;
        }
    }

    float inv = (deg > 0) ? 1.f / fmaxf(ssum, 1e-16f) : 0.f;
    if (F == 256) {
        size_t o = (size_t)n * 64;
        float4 rr = r4[o + lane], bb = b4[lane];
        h4[o + lane] = make_float4(acc0.x * inv + rr.x + bb.x, acc0.y * inv + rr.y + bb.y,
                                   acc0.z * inv + rr.z + bb.z, acc0.w * inv + rr.w + bb.w);
        rr = r4[o + 32 + lane]; bb = b4[32 + lane];
        h4[o + 32 + lane] = make_float4(acc1.x * inv + rr.x + bb.x, acc1.y * inv + rr.y + bb.y,
                                        acc1.z * inv + rr.z + bb.z, acc1.w * inv + rr.w + bb.w);
    } else {
        size_t o = (size_t)n * 32;
        float4 rr = r4[o + lane], bb = b4[lane];
        h4[o + lane] = make_float4(acc0.x * inv + rr.x + bb.x, acc0.y * inv + rr.y + bb.y,
                                   acc0.z * inv + rr.z + bb.z, acc0.w * inv + rr.w + bb.w);
    }
}

// ---------------- batch norm (double accumulation) ----------------
// invariant: g_sumd/g_sumsqd are zero at call entry; finalize re-zeros them.
#define BN_ROWS 256
__global__ __launch_bounds__(256) void bn_stats_kernel(int F) {
    int r0 = blockIdx.x * BN_ROWS;
    int r1 = min(r0 + BN_ROWS, Nn);
    for (int f = threadIdx.x; f < F; f += 256) {
        double s = 0.0, q = 0.0;
        for (int r = r0; r < r1; r++) {
            float v = g_h[(size_t)r * F + f];
            s += (double)v; q += (double)v * (double)v;
        }
        atomicAdd(&g_sumd[f], s);
        atomicAdd(&g_sumsqd[f], q);
    }
}
__global__ void bn_finalize_kernel(int F) {
    int f = threadIdx.x;
    if (f < F) {
        double mu = g_sumd[f] / (double)Nn;
        double var = g_sumsqd[f] / (double)Nn - mu * mu;
        if (var < 0.0) var = 0.0;
        g_mean[f] = (float)mu;
        g_inv[f] = (float)(1.0 / sqrt(var + 1e-5));
    }
    // re-zero for next use (maintains zero-at-entry invariant across replays)
    g_sumd[f] = 0.0;
    g_sumsqd[f] = 0.0;
}
__global__ void bn_apply_relu_kernel(const float* __restrict__ gam,
                                     const float* __restrict__ bet, int F) {
    int i = blockIdx.x * blockDim.x + threadIdx.x;
    if (i < Nn * F) {
        int f = i % F;
        float v = (g_h[i] - g_mean[f]) * g_inv[f] * gam[f] + bet[f];
        g_x1[i] = v > 0.f ? v : 0.f;
    }
}
__global__ void final_out_kernel(const float* __restrict__ gam,
                                 const float* __restrict__ bet,
                                 const float* __restrict__ x0,
                                 float* __restrict__ out) {
    int i = blockIdx.x * blockDim.x + threadIdx.x;
    if (i < Nn * IOd) {
        int f = i % IOd;
        float v = (g_h[i] - g_mean[f]) * g_inv[f] * gam[f] + bet[f] + x0[i];
        out[i] = v > 0.f ? v : 0.f;
    }
}

// ---------------- launch sequence ----------------
extern "C" void kernel_launch(void* const* d_in, const int* in_sizes, int n_in,
                              void* d_out, int out_size) {
    const float* x0  = (const float*)d_in[0];
    const void*  edg = d_in[1];
    const float* b1  = (const float*)d_in[6];
    const float* g1  = (const float*)d_in[7];
    const float* be1 = (const float*)d_in[8];
    const float* b2  = (const float*)d_in[13];
    const float* g2  = (const float*)d_in[14];
    const float* be2 = (const float*)d_in[15];
    float* out = (float*)d_out;

    W8 ws;
    ws.w[0] = (const float*)d_in[2];   // Wq1
    ws.w[1] = (const float*)d_in[3];   // Wk1
    ws.w[2] = (const float*)d_in[4];   // Wv1
    ws.w[3] = (const float*)d_in[5];   // Wr1
    ws.w[4] = (const float*)d_in[9];   // Wq2
    ws.w[5] = (const float*)d_in[10];  // Wk2
    ws.w[6] = (const float*)d_in[11];  // Wv2
    ws.w[7] = (const float*)d_in[12];  // Wr2

    __half *pqh, *pkh;
    float *pv, *pr, *px1, *pwt;
    cudaGetSymbolAddress((void**)&pqh, g_qh);
    cudaGetSymbolAddress((void**)&pkh, g_kh);
    cudaGetSymbolAddress((void**)&pv,  g_v);
    cudaGetSymbolAddress((void**)&pr,  g_r);
    cudaGetSymbolAddress((void**)&px1, g_x1);
    cudaGetSymbolAddress((void**)&pwt, g_wt);

    const int SMEM_GEMM = 4 * 128 * SROW * 4;   // 73728 bytes
    cudaFuncSetAttribute((const void*)fused_gemm_kernel<1>, cudaFuncAttributeMaxDynamicSharedMemorySize, SMEM_GEMM);
    cudaFuncSetAttribute((const void*)fused_gemm_kernel<2>, cudaFuncAttributeMaxDynamicSharedMemorySize, SMEM_GEMM);

    const int EDGE_BLOCKS = (Ee + 255) / 256;
    const int NODE_BLOCKS = (Nn + 255) / 256;
    const int NH_BLOCKS = (Nn * HIDd + 255) / 256;
    const int NI_BLOCKS = (Nn * IOd + 255) / 256;
    const int BN_BLOCKS = (Nn + BN_ROWS - 1) / BN_ROWS;
    const int ATTN_BLOCKS = (Nn * 32 + 255) / 256;
    const int MB = (Nn + 127) / 128;   // 391

    detect_zero_kernel<<<NODE_BLOCKS, 256>>>((const int*)edg);
    convert_count_kernel<<<EDGE_BLOCKS, 256>>>(edg);
    scan1_kernel<<<NB_SCAN, 1024>>>();
    scan2_kernel<<<1, 1>>>();
    scan3_kernel<<<NB_SCAN, 1024>>>();
    csr_scatter_kernel<<<EDGE_BLOCKS, 256>>>();
    transpose_all_kernel<<<1280, 256>>>(ws, pwt);

    // ---- layer 1 ----
    fused_gemm_kernel<1><<<dim3(MB, 8), 256, SMEM_GEMM>>>(x0, pwt + WT_L1, pqh, pkh, pv, pr, Nn);
    attn_kernel<256><<<ATTN_BLOCKS, 256>>>(b1);
    bn_stats_kernel<<<BN_BLOCKS, 256>>>(HIDd);
    bn_finalize_kernel<<<1, 256>>>(HIDd);
    bn_apply_relu_kernel<<<NH_BLOCKS, 256>>>(g1, be1, HIDd);

    // ---- layer 2 ----
    fused_gemm_kernel<2><<<dim3(MB, 6), 256, SMEM_GEMM>>>(px1, pwt + WT_L2, pqh, pkh, pv, pr, Nn);
    attn_kernel<128><<<ATTN_BLOCKS, 256>>>(b2);
    bn_stats_kernel<<<BN_BLOCKS, 256>>>(IOd);
    bn_finalize_kernel<<<1, 256>>>(IOd);
    final_out_kernel<<<NI_BLOCKS, 256>>>(g2, be2, x0, out);
}

// round 8
// speedup vs baseline: 2.0101x; 1.0581x over previous
#include <cuda_runtime.h>
#include <cuda_fp16.h>
#include <math.h>
#include <stdint.h>

// Problem constants (fixed by the reference)
#define Nn   50000
#define Ee   800000
#define IOd  128
#define HIDd 256
#define KQd  256

// ---------------- device scratch (no allocations allowed) ----------------
__device__ __half g_qh[Nn * KQd];
__device__ __half g_kh[Nn * KQd];
__device__ __half g_vh[Nn * HIDd];
__device__ float g_r[Nn * HIDd];
__device__ float g_h[Nn * HIDd];
__device__ float g_x1[Nn * HIDd];
__device__ float g_wt[327680];      // transposed weights (concatenated per layer)
__device__ int   g_src[Ee];
__device__ int   g_dst[Ee];
__device__ int   g_csr_src[Ee];
__device__ int   g_deg[Nn];
__device__ int   g_inc[Nn];
__device__ int   g_fill[Nn];
#define NB_SCAN 49
__device__ int   g_bsum[NB_SCAN];
__device__ int   g_boff[NB_SCAN];
__device__ double g_sumd[HIDd];     // zero at call entry; finalize re-zeros
__device__ double g_sumsqd[HIDd];
__device__ float g_mean[HIDd];
__device__ float g_inv[HIDd];
__device__ int   g_flag64[1];

#define WT_L1 0         // [1024 x 128]: Q1,K1,V1,R1
#define WT_L2 131072    // [768 x 256]:  Q2,K2,V2,R2

// ---------------- helpers ----------------
__device__ __forceinline__ uint32_t smem_u32(const void* p) {
    uint32_t a;
    asm("{ .reg .u64 t; cvta.to.shared.u64 t, %1; cvt.u32.u64 %0, t; }" : "=r"(a) : "l"(p));
    return a;
}
__device__ __forceinline__ void cp_async16(uint32_t sm, const void* g) {
    asm volatile("cp.async.cg.shared.global [%0], [%1], 16;" :: "r"(sm), "l"(g));
}
__device__ __forceinline__ void cp_commit() { asm volatile("cp.async.commit_group;"); }
__device__ __forceinline__ void cp_wait1() { asm volatile("cp.async.wait_group 1;"); }
__device__ __forceinline__ void cp_wait0() { asm volatile("cp.async.wait_group 0;"); }

// ---------------- all-weights transpose (one launch) ----------------
struct W8 { const float* w[8]; };
__global__ void transpose_all_kernel(W8 ws, float* __restrict__ Wt) {
    int i = blockIdx.x * 256 + threadIdx.x;
    if (i >= 327680) return;
    int seg, base, K, N, dst;
    if (i < 131072)      { seg = i >> 15;       base = seg << 15;          K = 128; N = 256; dst = seg * 32768; }
    else if (i < 262144) { seg = 4 + ((i - 131072) >> 16); base = 131072 + ((seg - 4) << 16); K = 256; N = 256; dst = 131072 + (seg - 4) * 65536; }
    else                 { seg = 6 + ((i - 262144) >> 15); base = 262144 + ((seg - 6) << 15); K = 256; N = 128; dst = 262144 + (seg - 6) * 32768; }
    int il = i - base;
    int k = il / N, n = il % N;
    Wt[dst + n * K + k] = ws.w[seg][il];
}

// ---------------- fused HMMA tf32 GEMM (4 outputs per layer) ----------------
#define SROW 36

template <int LAYER>
__global__ __launch_bounds__(256) void fused_gemm_kernel(
    const float* __restrict__ A, const float* __restrict__ BtAll,
    __half* __restrict__ Oq, __half* __restrict__ Ok,
    __half* __restrict__ Ov, float* __restrict__ Or, int M)
{
    constexpr int K = (LAYER == 1) ? 128 : 256;
    extern __shared__ float smem[];
    float* As = smem;
    float* Bs = smem + 2 * 128 * SROW;

    const int tid = threadIdx.x;
    const int wid = tid >> 5;
    const int lane = tid & 31;
    const int gID = lane >> 2;
    const int tig = lane & 3;
    const int wm = (wid & 1) * 64;
    const int wn = (wid >> 1) * 32;
    const int m0 = blockIdx.x * 128;
    const int y = blockIdx.y;
    const int nb0 = y * 128;

    float c[4][4][4] = {};
    constexpr int NC = K / 32;

    auto stage = [&](int cc, int buf) {
        const int k0 = cc * 32;
        float* ab = As + buf * (128 * SROW);
        float* bb = Bs + buf * (128 * SROW);
        #pragma unroll
        for (int i = 0; i < 4; i++) {
            int idx = tid + i * 256;
            int row = idx >> 3, g = idx & 7;
            int gr = m0 + row; if (gr >= M) gr = M - 1;
            cp_async16(smem_u32(ab + row * SROW + g * 4), A + (size_t)gr * K + k0 + g * 4);
        }
        #pragma unroll
        for (int i = 0; i < 4; i++) {
            int idx = tid + i * 256;
            int row = idx >> 3, g = idx & 7;
            cp_async16(smem_u32(bb + row * SROW + g * 4), BtAll + (size_t)(nb0 + row) * K + k0 + g * 4);
        }
        cp_commit();
    };

    stage(0, 0);
    for (int cc = 0; cc < NC; cc++) {
        const int buf = cc & 1;
        if (cc + 1 < NC) { stage(cc + 1, buf ^ 1); cp_wait1(); }
        else             { cp_wait0(); }
        __syncthreads();

        const float* ab = As + buf * (128 * SROW);
        const float* bb = Bs + buf * (128 * SROW);

        #pragma unroll
        for (int ks = 0; ks < 4; ks++) {
            const int kk = ks * 8;
            uint32_t af[4][4];
            #pragma unroll
            for (int mf = 0; mf < 4; mf++) {
                const float* base = ab + (wm + mf * 16) * SROW + kk;
                af[mf][0] = __float_as_uint(base[gID * SROW + tig]);
                af[mf][1] = __float_as_uint(base[(gID + 8) * SROW + tig]);
                af[mf][2] = __float_as_uint(base[gID * SROW + tig + 4]);
                af[mf][3] = __float_as_uint(base[(gID + 8) * SROW + tig + 4]);
            }
            uint32_t bf[4][2];
            #pragma unroll
            for (int nf = 0; nf < 4; nf++) {
                const float* base = bb + (wn + nf * 8 + gID) * SROW + kk;
                bf[nf][0] = __float_as_uint(base[tig]);
                bf[nf][1] = __float_as_uint(base[tig + 4]);
            }
            #pragma unroll
            for (int mf = 0; mf < 4; mf++)
                #pragma unroll
                for (int nf = 0; nf < 4; nf++)
                    asm volatile(
                        "mma.sync.aligned.m16n8k8.row.col.f32.tf32.tf32.f32 "
                        "{%0,%1,%2,%3}, {%4,%5,%6,%7}, {%8,%9}, {%0,%1,%2,%3};"
                        : "+f"(c[mf][nf][0]), "+f"(c[mf][nf][1]),
                          "+f"(c[mf][nf][2]), "+f"(c[mf][nf][3])
                        : "r"(af[mf][0]), "r"(af[mf][1]), "r"(af[mf][2]), "r"(af[mf][3]),
                          "r"(bf[nf][0]), "r"(bf[nf][1]));
        }
        __syncthreads();
    }

    // output routing (q,k,v fp16; r fp32)
    __half* hout = nullptr; float* fout = nullptr;
    int Nout, cb;
    if (LAYER == 1) {
        int oi = y >> 1; cb = (y & 1) * 128; Nout = 256;
        if (oi == 0) hout = Oq; else if (oi == 1) hout = Ok;
        else if (oi == 2) hout = Ov; else fout = Or;
    } else {
        if (y < 4) { int oi = y >> 1; cb = (y & 1) * 128; Nout = 256; hout = (oi == 0) ? Oq : Ok; }
        else       { cb = 0; Nout = 128; if (y == 4) hout = Ov; else fout = Or; }
    }

    #pragma unroll
    for (int mf = 0; mf < 4; mf++) {
        int row = m0 + wm + mf * 16 + gID;
        #pragma unroll
        for (int nf = 0; nf < 4; nf++) {
            int col = cb + wn + nf * 8 + tig * 2;
            if (hout) {
                if (row < M)
                    *(__half2*)(hout + (size_t)row * Nout + col) = __floats2half2_rn(c[mf][nf][0], c[mf][nf][1]);
                if (row + 8 < M)
                    *(__half2*)(hout + (size_t)(row + 8) * Nout + col) = __floats2half2_rn(c[mf][nf][2], c[mf][nf][3]);
            } else {
                if (row < M)
                    *(float2*)(fout + (size_t)row * Nout + col) = make_float2(c[mf][nf][0], c[mf][nf][1]);
                if (row + 8 < M)
                    *(float2*)(fout + (size_t)(row + 8) * Nout + col) = make_float2(c[mf][nf][2], c[mf][nf][3]);
            }
        }
    }
}

// ---------------- setup: zero + edge dtype detect ----------------
__global__ void detect_zero_kernel(const int* __restrict__ ew) {
    int i = blockIdx.x * blockDim.x + threadIdx.x;
    if (i < Nn) { g_deg[i] = 0; g_fill[i] = 0; }
    if (blockIdx.x == 0) {
        __shared__ int nz;
        if (threadIdx.x == 0) nz = 0;
        __syncthreads();
        int stride = Ee / 256;
        int idx = 2 * (threadIdx.x * stride) + 1;
        if (ew[idx] != 0) atomicOr(&nz, 1);
        __syncthreads();
        if (threadIdx.x == 0) g_flag64[0] = nz ? 0 : 1;
    }
}

__global__ void convert_count_kernel(const void* __restrict__ edges) {
    int e = blockIdx.x * blockDim.x + threadIdx.x;
    if (e >= Ee) return;
    int s, d;
    if (g_flag64[0]) {
        const long long* p = (const long long*)edges;
        s = (int)p[e]; d = (int)p[Ee + e];
    } else {
        const int* p = (const int*)edges;
        s = p[e]; d = p[Ee + e];
    }
    g_src[e] = s; g_dst[e] = d;
    atomicAdd(&g_deg[d], 1);
}

// ---------------- CSR scan + scatter ----------------
__global__ void scan1_kernel() {
    __shared__ int sm[1024];
    int i = blockIdx.x * 1024 + threadIdx.x;
    int v = (i < Nn) ? g_deg[i] : 0;
    sm[threadIdx.x] = v;
    __syncthreads();
    for (int off = 1; off < 1024; off <<= 1) {
        int t = (threadIdx.x >= off) ? sm[threadIdx.x - off] : 0;
        __syncthreads();
        sm[threadIdx.x] += t;
        __syncthreads();
    }
    if (i < Nn) g_inc[i] = sm[threadIdx.x];
    if (threadIdx.x == 1023) g_bsum[blockIdx.x] = sm[1023];
}
__global__ void scan2_kernel() {
    int acc = 0;
    for (int b = 0; b < NB_SCAN; b++) { g_boff[b] = acc; acc += g_bsum[b]; }
}
__global__ void scan3_kernel() {
    int i = blockIdx.x * 1024 + threadIdx.x;
    if (i < Nn) g_inc[i] += g_boff[blockIdx.x];
}
__global__ void csr_scatter_kernel() {
    int e = blockIdx.x * blockDim.x + threadIdx.x;
    if (e >= Ee) return;
    int d = g_dst[e];
    int pos = g_inc[d] - g_deg[d] + atomicAdd(&g_fill[d], 1);
    g_csr_src[pos] = g_src[e];
}

// ---------------- warp-per-node attention, online softmax, unroll 2 --------
__device__ __forceinline__ float dot8h(uint4 a, uint4 b) {
    const __half2* ah = (const __half2*)&a;
    const __half2* bh = (const __half2*)&b;
    float p = 0.f;
    #pragma unroll
    for (int i = 0; i < 4; i++) {
        float2 fa = __half22float2(ah[i]);
        float2 fb = __half22float2(bh[i]);
        p += fa.x * fb.x + fa.y * fb.y;
    }
    return p;
}
__device__ __forceinline__ void unpack8h(uint4 a, float* f) {
    const __half2* ah = (const __half2*)&a;
    #pragma unroll
    for (int i = 0; i < 4; i++) {
        float2 t = __half22float2(ah[i]);
        f[2 * i] = t.x; f[2 * i + 1] = t.y;
    }
}
__device__ __forceinline__ void unpack4h(uint2 a, float* f) {
    const __half2* ah = (const __half2*)&a;
    #pragma unroll
    for (int i = 0; i < 2; i++) {
        float2 t = __half22float2(ah[i]);
        f[2 * i] = t.x; f[2 * i + 1] = t.y;
    }
}

template <int F>
__global__ __launch_bounds__(256) void attn_kernel(const float* __restrict__ bias) {
    int n = (blockIdx.x * blockDim.x + threadIdx.x) >> 5;
    int lane = threadIdx.x & 31;
    if (n >= Nn) return;

    int deg = g_deg[n];
    int base = g_inc[n] - deg;

    const uint4* qh = (const uint4*)g_qh;
    const uint4* kh = (const uint4*)g_kh;
    constexpr int EPL = F / 32;     // elements per lane (8 or 4)
    float acc[EPL];
    #pragma unroll
    for (int i = 0; i < EPL; i++) acc[i] = 0.f;
    float ssum = 0.f;

    if (deg > 0) {
        uint4 qreg = qh[(size_t)n * 32 + lane];
        float mx = -INFINITY;
        int j = 0;
        for (; j + 2 <= deg; j += 2) {
            int s0 = g_csr_src[base + j];
            int s1 = g_csr_src[base + j + 1];
            float p0 = dot8h(qreg, kh[(size_t)s0 * 32 + lane]);
            float p1 = dot8h(qreg, kh[(size_t)s1 * 32 + lane]);
            #pragma unroll
            for (int off = 16; off; off >>= 1) {
                p0 += __shfl_xor_sync(0xffffffffu, p0, off);
                p1 += __shfl_xor_sync(0xffffffffu, p1, off);
            }
            p0 *= 0.0625f; p1 *= 0.0625f;
            float v0[EPL], v1[EPL];
            if (F == 256) {
                unpack8h(((const uint4*)g_vh)[(size_t)s0 * 32 + lane], v0);
                unpack8h(((const uint4*)g_vh)[(size_t)s1 * 32 + lane], v1);
            } else {
                unpack4h(((const uint2*)g_vh)[(size_t)s0 * 32 + lane], v0);
                unpack4h(((const uint2*)g_vh)[(size_t)s1 * 32 + lane], v1);
            }
            float mnew = fmaxf(mx, fmaxf(p0, p1));
            float corr = expf(mx - mnew);
            float e0 = expf(p0 - mnew);
            float e1 = expf(p1 - mnew);
            ssum = ssum * corr + e0 + e1;
            #pragma unroll
            for (int i = 0; i < EPL; i++)
                acc[i] = acc[i] * corr + e0 * v0[i] + e1 * v1[i];
            mx = mnew;
        }
        if (j < deg) {
            int s0 = g_csr_src[base + j];
            float p0 = dot8h(qreg, kh[(size_t)s0 * 32 + lane]);
            #pragma unroll
            for (int off = 16; off; off >>= 1)
                p0 += __shfl_xor_sync(0xffffffffu, p0, off);
            p0 *= 0.0625f;
            float v0[EPL];
            if (F == 256) unpack8h(((const uint4*)g_vh)[(size_t)s0 * 32 + lane], v0);
            else          unpack4h(((const uint2*)g_vh)[(size_t)s0 * 32 + lane], v0);
            float mnew = fmaxf(mx, p0);
            float corr = expf(mx - mnew);
            float e0 = expf(p0 - mnew);
            ssum = ssum * corr + e0;
            #pragma unroll
            for (int i = 0; i < EPL; i++)
                acc[i] = acc[i] * corr + e0 * v0[i];
            mx = mnew;
        }
    }

    float inv = (deg > 0) ? 1.f / fmaxf(ssum, 1e-16f) : 0.f;
    // write h = acc*inv + r + bias ; lane owns elements [lane*EPL, lane*EPL+EPL)
    const float4* r4 = (const float4*)g_r;
    const float4* b4 = (const float4*)bias;
    float4* h4 = (float4*)g_h;
    size_t o = (size_t)n * (F / 4) + lane * (EPL / 4);
    int bo = lane * (EPL / 4);
    #pragma unroll
    for (int t = 0; t < EPL / 4; t++) {
        float4 rr = r4[o + t], bb = b4[bo + t];
        h4[o + t] = make_float4(acc[4 * t + 0] * inv + rr.x + bb.x,
                                acc[4 * t + 1] * inv + rr.y + bb.y,
                                acc[4 * t + 2] * inv + rr.z + bb.z,
                                acc[4 * t + 3] * inv + rr.w + bb.w);
    }
}

// ---------------- batch norm (double accumulation) ----------------
#define BN_ROWS 256
__global__ __launch_bounds__(256) void bn_stats_kernel(int F) {
    int r0 = blockIdx.x * BN_ROWS;
    int r1 = min(r0 + BN_ROWS, Nn);
    for (int f = threadIdx.x; f < F; f += 256) {
        double s = 0.0, q = 0.0;
        for (int r = r0; r < r1; r++) {
            float v = g_h[(size_t)r * F + f];
            s += (double)v; q += (double)v * (double)v;
        }
        atomicAdd(&g_sumd[f], s);
        atomicAdd(&g_sumsqd[f], q);
    }
}
__global__ void bn_finalize_kernel(int F) {
    int f = threadIdx.x;
    if (f < F) {
        double mu = g_sumd[f] / (double)Nn;
        double var = g_sumsqd[f] / (double)Nn - mu * mu;
        if (var < 0.0) var = 0.0;
        g_mean[f] = (float)mu;
        g_inv[f] = (float)(1.0 / sqrt(var + 1e-5));
    }
    g_sumd[f] = 0.0;
    g_sumsqd[f] = 0.0;
}
__global__ void bn_apply_relu_kernel(const float* __restrict__ gam,
                                     const float* __restrict__ bet, int F) {
    int i = blockIdx.x * blockDim.x + threadIdx.x;
    if (i < Nn * F) {
        int f = i % F;
        float v = (g_h[i] - g_mean[f]) * g_inv[f] * gam[f] + bet[f];
        g_x1[i] = v > 0.f ? v : 0.f;
    }
}
__global__ void final_out_kernel(const float* __restrict__ gam,
                                 const float* __restrict__ bet,
                                 const float* __restrict__ x0,
                                 float* __restrict__ out) {
    int i = blockIdx.x * blockDim.x + threadIdx.x;
    if (i < Nn * IOd) {
        int f = i % IOd;
        float v = (g_h[i] - g_mean[f]) * g_inv[f] * gam[f] + bet[f] + x0[i];
        out[i] = v > 0.f ? v : 0.f;
    }
}

// ---------------- launch sequence ----------------
extern "C" void kernel_launch(void* const* d_in, const int* in_sizes, int n_in,
                              void* d_out, int out_size) {
    const float* x0  = (const float*)d_in[0];
    const void*  edg = d_in[1];
    const float* b1  = (const float*)d_in[6];
    const float* g1  = (const float*)d_in[7];
    const float* be1 = (const float*)d_in[8];
    const float* b2  = (const float*)d_in[13];
    const float* g2  = (const float*)d_in[14];
    const float* be2 = (const float*)d_in[15];
    float* out = (float*)d_out;

    W8 ws;
    ws.w[0] = (const float*)d_in[2];
    ws.w[1] = (const float*)d_in[3];
    ws.w[2] = (const float*)d_in[4];
    ws.w[3] = (const float*)d_in[5];
    ws.w[4] = (const float*)d_in[9];
    ws.w[5] = (const float*)d_in[10];
    ws.w[6] = (const float*)d_in[11];
    ws.w[7] = (const float*)d_in[12];

    __half *pqh, *pkh, *pvh;
    float *pr, *px1, *pwt;
    cudaGetSymbolAddress((void**)&pqh, g_qh);
    cudaGetSymbolAddress((void**)&pkh, g_kh);
    cudaGetSymbolAddress((void**)&pvh, g_vh);
    cudaGetSymbolAddress((void**)&pr,  g_r);
    cudaGetSymbolAddress((void**)&px1, g_x1);
    cudaGetSymbolAddress((void**)&pwt, g_wt);

    const int SMEM_GEMM = 4 * 128 * SROW * 4;
    cudaFuncSetAttribute((const void*)fused_gemm_kernel<1>, cudaFuncAttributeMaxDynamicSharedMemorySize, SMEM_GEMM);
    cudaFuncSetAttribute((const void*)fused_gemm_kernel<2>, cudaFuncAttributeMaxDynamicSharedMemorySize, SMEM_GEMM);

    const int EDGE_BLOCKS = (Ee + 255) / 256;
    const int NODE_BLOCKS = (Nn + 255) / 256;
    const int NH_BLOCKS = (Nn * HIDd + 255) / 256;
    const int NI_BLOCKS = (Nn * IOd + 255) / 256;
    const int BN_BLOCKS = (Nn + BN_ROWS - 1) / BN_ROWS;
    const int ATTN_BLOCKS = (Nn * 32 + 255) / 256;
    const int MB = (Nn + 127) / 128;

    detect_zero_kernel<<<NODE_BLOCKS, 256>>>((const int*)edg);
    convert_count_kernel<<<EDGE_BLOCKS, 256>>>(edg);
    scan1_kernel<<<NB_SCAN, 1024>>>();
    scan2_kernel<<<1, 1>>>();
    scan3_kernel<<<NB_SCAN, 1024>>>();
    csr_scatter_kernel<<<EDGE_BLOCKS, 256>>>();
    transpose_all_kernel<<<1280, 256>>>(ws, pwt);

    // ---- layer 1 ----
    fused_gemm_kernel<1><<<dim3(MB, 8), 256, SMEM_GEMM>>>(x0, pwt + WT_L1, pqh, pkh, pvh, pr, Nn);
    attn_kernel<256><<<ATTN_BLOCKS, 256>>>(b1);
    bn_stats_kernel<<<BN_BLOCKS, 256>>>(HIDd);
    bn_finalize_kernel<<<1, 256>>>(HIDd);
    bn_apply_relu_kernel<<<NH_BLOCKS, 256>>>(g1, be1, HIDd);

    // ---- layer 2 ----
    fused_gemm_kernel<2><<<dim3(MB, 6), 256, SMEM_GEMM>>>(px1, pwt + WT_L2, pqh, pkh, pvh, pr, Nn);
    attn_kernel<128><<<ATTN_BLOCKS, 256>>>(b2);
    bn_stats_kernel<<<BN_BLOCKS, 256>>>(IOd);
    bn_finalize_kernel<<<1, 256>>>(IOd);
    final_out_kernel<<<NI_BLOCKS, 256>>>(g2, be2, x0, out);
}

// round 9
// speedup vs baseline: 2.4073x; 1.1976x over previous
#include <cuda_runtime.h>
#include <cuda_fp16.h>
#include <math.h>
#include <stdint.h>

// Problem constants (fixed by the reference)
#define Nn   50000
#define Ee   800000
#define IOd  128
#define HIDd 256
#define KQd  256

// ---------------- device scratch (no allocations allowed) ----------------
__device__ __half g_qh[Nn * KQd];
__device__ __half g_kh[Nn * KQd];
__device__ __half g_vh[Nn * HIDd];
__device__ float g_r[Nn * HIDd];
__device__ float g_h[Nn * HIDd];
__device__ float g_x1[Nn * HIDd];
__device__ float g_wt[327680];
__device__ int   g_src[Ee];
__device__ int   g_dst[Ee];
__device__ int   g_csr_src[Ee];
__device__ int   g_deg[Nn];
__device__ int   g_inc[Nn];
__device__ int   g_fill[Nn];
#define NB_SCAN 49
__device__ int   g_bsum[NB_SCAN];
__device__ int   g_boff[NB_SCAN];
__device__ float g_sumf[HIDd];      // zero at call entry; finalize re-zeros
__device__ float g_sumsqf[HIDd];
__device__ float g_mean[HIDd];
__device__ float g_inv[HIDd];
__device__ int   g_flag64[1];

#define WT_L1 0         // [1024 x 128]: Q1,K1,V1,R1
#define WT_L2 131072    // [768 x 256]:  Q2,K2,V2,R2

// ---------------- helpers ----------------
__device__ __forceinline__ uint32_t smem_u32(const void* p) {
    uint32_t a;
    asm("{ .reg .u64 t; cvta.to.shared.u64 t, %1; cvt.u32.u64 %0, t; }" : "=r"(a) : "l"(p));
    return a;
}
__device__ __forceinline__ void cp_async16(uint32_t sm, const void* g) {
    asm volatile("cp.async.cg.shared.global [%0], [%1], 16;" :: "r"(sm), "l"(g));
}
__device__ __forceinline__ void cp_commit() { asm volatile("cp.async.commit_group;"); }
__device__ __forceinline__ void cp_wait1() { asm volatile("cp.async.wait_group 1;"); }
__device__ __forceinline__ void cp_wait0() { asm volatile("cp.async.wait_group 0;"); }

// ---------------- all-weights transpose (one launch) ----------------
struct W8 { const float* w[8]; };
__global__ void transpose_all_kernel(W8 ws, float* __restrict__ Wt) {
    int i = blockIdx.x * 256 + threadIdx.x;
    if (i >= 327680) return;
    int seg, base, K, N, dst;
    if (i < 131072)      { seg = i >> 15;       base = seg << 15;          K = 128; N = 256; dst = seg * 32768; }
    else if (i < 262144) { seg = 4 + ((i - 131072) >> 16); base = 131072 + ((seg - 4) << 16); K = 256; N = 256; dst = 131072 + (seg - 4) * 65536; }
    else                 { seg = 6 + ((i - 262144) >> 15); base = 262144 + ((seg - 6) << 15); K = 256; N = 128; dst = 262144 + (seg - 6) * 32768; }
    int il = i - base;
    int k = il / N, n = il % N;
    Wt[dst + n * K + k] = ws.w[seg][il];
}

// ---------------- fused HMMA tf32 GEMM (4 outputs per layer) ----------------
#define SROW 36

template <int LAYER>
__global__ __launch_bounds__(256) void fused_gemm_kernel(
    const float* __restrict__ A, const float* __restrict__ BtAll,
    __half* __restrict__ Oq, __half* __restrict__ Ok,
    __half* __restrict__ Ov, float* __restrict__ Or, int M)
{
    constexpr int K = (LAYER == 1) ? 128 : 256;
    extern __shared__ float smem[];
    float* As = smem;
    float* Bs = smem + 2 * 128 * SROW;

    const int tid = threadIdx.x;
    const int wid = tid >> 5;
    const int lane = tid & 31;
    const int gID = lane >> 2;
    const int tig = lane & 3;
    const int wm = (wid & 1) * 64;
    const int wn = (wid >> 1) * 32;
    const int m0 = blockIdx.x * 128;
    const int y = blockIdx.y;
    const int nb0 = y * 128;

    float c[4][4][4] = {};
    constexpr int NC = K / 32;

    auto stage = [&](int cc, int buf) {
        const int k0 = cc * 32;
        float* ab = As + buf * (128 * SROW);
        float* bb = Bs + buf * (128 * SROW);
        #pragma unroll
        for (int i = 0; i < 4; i++) {
            int idx = tid + i * 256;
            int row = idx >> 3, g = idx & 7;
            int gr = m0 + row; if (gr >= M) gr = M - 1;
            cp_async16(smem_u32(ab + row * SROW + g * 4), A + (size_t)gr * K + k0 + g * 4);
        }
        #pragma unroll
        for (int i = 0; i < 4; i++) {
            int idx = tid + i * 256;
            int row = idx >> 3, g = idx & 7;
            cp_async16(smem_u32(bb + row * SROW + g * 4), BtAll + (size_t)(nb0 + row) * K + k0 + g * 4);
        }
        cp_commit();
    };

    stage(0, 0);
    for (int cc = 0; cc < NC; cc++) {
        const int buf = cc & 1;
        if (cc + 1 < NC) { stage(cc + 1, buf ^ 1); cp_wait1(); }
        else             { cp_wait0(); }
        __syncthreads();

        const float* ab = As + buf * (128 * SROW);
        const float* bb = Bs + buf * (128 * SROW);

        #pragma unroll
        for (int ks = 0; ks < 4; ks++) {
            const int kk = ks * 8;
            uint32_t af[4][4];
            #pragma unroll
            for (int mf = 0; mf < 4; mf++) {
                const float* base = ab + (wm + mf * 16) * SROW + kk;
                af[mf][0] = __float_as_uint(base[gID * SROW + tig]);
                af[mf][1] = __float_as_uint(base[(gID + 8) * SROW + tig]);
                af[mf][2] = __float_as_uint(base[gID * SROW + tig + 4]);
                af[mf][3] = __float_as_uint(base[(gID + 8) * SROW + tig + 4]);
            }
            uint32_t bf[4][2];
            #pragma unroll
            for (int nf = 0; nf < 4; nf++) {
                const float* base = bb + (wn + nf * 8 + gID) * SROW + kk;
                bf[nf][0] = __float_as_uint(base[tig]);
                bf[nf][1] = __float_as_uint(base[tig + 4]);
            }
            #pragma unroll
            for (int mf = 0; mf < 4; mf++)
                #pragma unroll
                for (int nf = 0; nf < 4; nf++)
                    asm volatile(
                        "mma.sync.aligned.m16n8k8.row.col.f32.tf32.tf32.f32 "
                        "{%0,%1,%2,%3}, {%4,%5,%6,%7}, {%8,%9}, {%0,%1,%2,%3};"
                        : "+f"(c[mf][nf][0]), "+f"(c[mf][nf][1]),
                          "+f"(c[mf][nf][2]), "+f"(c[mf][nf][3])
                        : "r"(af[mf][0]), "r"(af[mf][1]), "r"(af[mf][2]), "r"(af[mf][3]),
                          "r"(bf[nf][0]), "r"(bf[nf][1]));
        }
        __syncthreads();
    }

    __half* hout = nullptr; float* fout = nullptr;
    int Nout, cb;
    if (LAYER == 1) {
        int oi = y >> 1; cb = (y & 1) * 128; Nout = 256;
        if (oi == 0) hout = Oq; else if (oi == 1) hout = Ok;
        else if (oi == 2) hout = Ov; else fout = Or;
    } else {
        if (y < 4) { int oi = y >> 1; cb = (y & 1) * 128; Nout = 256; hout = (oi == 0) ? Oq : Ok; }
        else       { cb = 0; Nout = 128; if (y == 4) hout = Ov; else fout = Or; }
    }

    #pragma unroll
    for (int mf = 0; mf < 4; mf++) {
        int row = m0 + wm + mf * 16 + gID;
        #pragma unroll
        for (int nf = 0; nf < 4; nf++) {
            int col = cb + wn + nf * 8 + tig * 2;
            if (hout) {
                if (row < M)
                    *(__half2*)(hout + (size_t)row * Nout + col) = __floats2half2_rn(c[mf][nf][0], c[mf][nf][1]);
                if (row + 8 < M)
                    *(__half2*)(hout + (size_t)(row + 8) * Nout + col) = __floats2half2_rn(c[mf][nf][2], c[mf][nf][3]);
            } else {
                if (row < M)
                    *(float2*)(fout + (size_t)row * Nout + col) = make_float2(c[mf][nf][0], c[mf][nf][1]);
                if (row + 8 < M)
                    *(float2*)(fout + (size_t)(row + 8) * Nout + col) = make_float2(c[mf][nf][2], c[mf][nf][3]);
            }
        }
    }
}

// ---------------- setup: zero + edge dtype detect ----------------
__global__ void detect_zero_kernel(const int* __restrict__ ew) {
    int i = blockIdx.x * blockDim.x + threadIdx.x;
    if (i < Nn) { g_deg[i] = 0; g_fill[i] = 0; }
    if (blockIdx.x == 0) {
        __shared__ int nz;
        if (threadIdx.x == 0) nz = 0;
        __syncthreads();
        int stride = Ee / 256;
        int idx = 2 * (threadIdx.x * stride) + 1;
        if (ew[idx] != 0) atomicOr(&nz, 1);
        __syncthreads();
        if (threadIdx.x == 0) g_flag64[0] = nz ? 0 : 1;
    }
}

__global__ void convert_count_kernel(const void* __restrict__ edges) {
    int e = blockIdx.x * blockDim.x + threadIdx.x;
    if (e >= Ee) return;
    int s, d;
    if (g_flag64[0]) {
        const long long* p = (const long long*)edges;
        s = (int)p[e]; d = (int)p[Ee + e];
    } else {
        const int* p = (const int*)edges;
        s = p[e]; d = p[Ee + e];
    }
    g_src[e] = s; g_dst[e] = d;
    atomicAdd(&g_deg[d], 1);
}

// ---------------- CSR scan + scatter ----------------
__global__ void scan1_kernel() {
    __shared__ int sm[1024];
    int i = blockIdx.x * 1024 + threadIdx.x;
    int v = (i < Nn) ? g_deg[i] : 0;
    sm[threadIdx.x] = v;
    __syncthreads();
    for (int off = 1; off < 1024; off <<= 1) {
        int t = (threadIdx.x >= off) ? sm[threadIdx.x - off] : 0;
        __syncthreads();
        sm[threadIdx.x] += t;
        __syncthreads();
    }
    if (i < Nn) g_inc[i] = sm[threadIdx.x];
    if (threadIdx.x == 1023) g_bsum[blockIdx.x] = sm[1023];
}
__global__ void scan2_kernel() {
    int acc = 0;
    for (int b = 0; b < NB_SCAN; b++) { g_boff[b] = acc; acc += g_bsum[b]; }
}
__global__ void scan3_kernel() {
    int i = blockIdx.x * 1024 + threadIdx.x;
    if (i < Nn) g_inc[i] += g_boff[blockIdx.x];
}
__global__ void csr_scatter_kernel() {
    int e = blockIdx.x * blockDim.x + threadIdx.x;
    if (e >= Ee) return;
    int d = g_dst[e];
    int pos = g_inc[d] - g_deg[d] + atomicAdd(&g_fill[d], 1);
    g_csr_src[pos] = g_src[e];
}

// ---------------- attention: online softmax, unroll 4, fused BN stats ------
__device__ __forceinline__ float dot8h(uint4 a, uint4 b) {
    const __half2* ah = (const __half2*)&a;
    const __half2* bh = (const __half2*)&b;
    float p = 0.f;
    #pragma unroll
    for (int i = 0; i < 4; i++) {
        float2 fa = __half22float2(ah[i]);
        float2 fb = __half22float2(bh[i]);
        p += fa.x * fb.x + fa.y * fb.y;
    }
    return p;
}
__device__ __forceinline__ void unpack8h(uint4 a, float* f) {
    const __half2* ah = (const __half2*)&a;
    #pragma unroll
    for (int i = 0; i < 4; i++) {
        float2 t = __half22float2(ah[i]);
        f[2 * i] = t.x; f[2 * i + 1] = t.y;
    }
}
__device__ __forceinline__ void unpack4h(uint2 a, float* f) {
    const __half2* ah = (const __half2*)&a;
    #pragma unroll
    for (int i = 0; i < 2; i++) {
        float2 t = __half22float2(ah[i]);
        f[2 * i] = t.x; f[2 * i + 1] = t.y;
    }
}

template <int F>
__global__ __launch_bounds__(256) void attn_kernel(const float* __restrict__ bias) {
    __shared__ float ssum[F], ssq[F];
    int tid = threadIdx.x;
    int n = (blockIdx.x * blockDim.x + tid) >> 5;
    int lane = tid & 31;
    if (tid < F) { ssum[tid] = 0.f; ssq[tid] = 0.f; }
    __syncthreads();

    constexpr int EPL = F / 32;
    float hv[EPL];

    if (n < Nn) {
        int deg = g_deg[n];
        int base = g_inc[n] - deg;

        const uint4* qh = (const uint4*)g_qh;
        const uint4* kh = (const uint4*)g_kh;
        float acc[EPL];
        #pragma unroll
        for (int i = 0; i < EPL; i++) acc[i] = 0.f;
        float ssm = 0.f;

        if (deg > 0) {
            uint4 qreg = qh[(size_t)n * 32 + lane];
            float mx = -INFINITY;
            int j = 0;
            for (; j + 4 <= deg; j += 4) {
                int s0 = g_csr_src[base + j];
                int s1 = g_csr_src[base + j + 1];
                int s2 = g_csr_src[base + j + 2];
                int s3 = g_csr_src[base + j + 3];
                float p0 = dot8h(qreg, kh[(size_t)s0 * 32 + lane]);
                float p1 = dot8h(qreg, kh[(size_t)s1 * 32 + lane]);
                float p2 = dot8h(qreg, kh[(size_t)s2 * 32 + lane]);
                float p3 = dot8h(qreg, kh[(size_t)s3 * 32 + lane]);
                #pragma unroll
                for (int off = 16; off; off >>= 1) {
                    p0 += __shfl_xor_sync(0xffffffffu, p0, off);
                    p1 += __shfl_xor_sync(0xffffffffu, p1, off);
                    p2 += __shfl_xor_sync(0xffffffffu, p2, off);
                    p3 += __shfl_xor_sync(0xffffffffu, p3, off);
                }
                p0 *= 0.0625f; p1 *= 0.0625f; p2 *= 0.0625f; p3 *= 0.0625f;
                float v0[EPL], v1[EPL], v2[EPL], v3[EPL];
                if (F == 256) {
                    unpack8h(((const uint4*)g_vh)[(size_t)s0 * 32 + lane], v0);
                    unpack8h(((const uint4*)g_vh)[(size_t)s1 * 32 + lane], v1);
                    unpack8h(((const uint4*)g_vh)[(size_t)s2 * 32 + lane], v2);
                    unpack8h(((const uint4*)g_vh)[(size_t)s3 * 32 + lane], v3);
                } else {
                    unpack4h(((const uint2*)g_vh)[(size_t)s0 * 32 + lane], v0);
                    unpack4h(((const uint2*)g_vh)[(size_t)s1 * 32 + lane], v1);
                    unpack4h(((const uint2*)g_vh)[(size_t)s2 * 32 + lane], v2);
                    unpack4h(((const uint2*)g_vh)[(size_t)s3 * 32 + lane], v3);
                }
                float mnew = fmaxf(fmaxf(mx, fmaxf(p0, p1)), fmaxf(p2, p3));
                float corr = expf(mx - mnew);
                float e0 = expf(p0 - mnew);
                float e1 = expf(p1 - mnew);
                float e2 = expf(p2 - mnew);
                float e3 = expf(p3 - mnew);
                ssm = ssm * corr + e0 + e1 + e2 + e3;
                #pragma unroll
                for (int i = 0; i < EPL; i++)
                    acc[i] = acc[i] * corr + e0 * v0[i] + e1 * v1[i] + e2 * v2[i] + e3 * v3[i];
                mx = mnew;
            }
            for (; j < deg; j++) {
                int s0 = g_csr_src[base + j];
                float p0 = dot8h(qreg, kh[(size_t)s0 * 32 + lane]);
                #pragma unroll
                for (int off = 16; off; off >>= 1)
                    p0 += __shfl_xor_sync(0xffffffffu, p0, off);
                p0 *= 0.0625f;
                float v0[EPL];
                if (F == 256) unpack8h(((const uint4*)g_vh)[(size_t)s0 * 32 + lane], v0);
                else          unpack4h(((const uint2*)g_vh)[(size_t)s0 * 32 + lane], v0);
                float mnew = fmaxf(mx, p0);
                float corr = expf(mx - mnew);
                float e0 = expf(p0 - mnew);
                ssm = ssm * corr + e0;
                #pragma unroll
                for (int i = 0; i < EPL; i++)
                    acc[i] = acc[i] * corr + e0 * v0[i];
                mx = mnew;
            }
        }

        float inv = (deg > 0) ? 1.f / fmaxf(ssm, 1e-16f) : 0.f;
        const float4* r4 = (const float4*)g_r;
        const float4* b4 = (const float4*)bias;
        float4* h4 = (float4*)g_h;
        size_t o = (size_t)n * (F / 4) + lane * (EPL / 4);
        int bo = lane * (EPL / 4);
        #pragma unroll
        for (int t = 0; t < EPL / 4; t++) {
            float4 rr = r4[o + t], bb = b4[bo + t];
            hv[4 * t + 0] = acc[4 * t + 0] * inv + rr.x + bb.x;
            hv[4 * t + 1] = acc[4 * t + 1] * inv + rr.y + bb.y;
            hv[4 * t + 2] = acc[4 * t + 2] * inv + rr.z + bb.z;
            hv[4 * t + 3] = acc[4 * t + 3] * inv + rr.w + bb.w;
            h4[o + t] = make_float4(hv[4 * t + 0], hv[4 * t + 1], hv[4 * t + 2], hv[4 * t + 3]);
        }
        // per-block BN partial sums
        #pragma unroll
        for (int i = 0; i < EPL; i++) {
            int f = lane * EPL + i;
            atomicAdd(&ssum[f], hv[i]);
            atomicAdd(&ssq[f], hv[i] * hv[i]);
        }
    }
    __syncthreads();
    if (tid < F) {
        atomicAdd(&g_sumf[tid], ssum[tid]);
        atomicAdd(&g_sumsqf[tid], ssq[tid]);
    }
}

// ---------------- batch norm finalize / apply ----------------
__global__ void bn_finalize_kernel(int F) {
    int f = threadIdx.x;
    if (f < F) {
        double mu = (double)g_sumf[f] / (double)Nn;
        double var = (double)g_sumsqf[f] / (double)Nn - mu * mu;
        if (var < 0.0) var = 0.0;
        g_mean[f] = (float)mu;
        g_inv[f] = (float)(1.0 / sqrt(var + 1e-5));
    }
    g_sumf[f] = 0.f;
    g_sumsqf[f] = 0.f;
}
__global__ void bn_apply_relu_kernel(const float* __restrict__ gam,
                                     const float* __restrict__ bet, int F) {
    int i = blockIdx.x * blockDim.x + threadIdx.x;
    if (i < Nn * F) {
        int f = i % F;
        float v = (g_h[i] - g_mean[f]) * g_inv[f] * gam[f] + bet[f];
        g_x1[i] = v > 0.f ? v : 0.f;
    }
}
__global__ void final_out_kernel(const float* __restrict__ gam,
                                 const float* __restrict__ bet,
                                 const float* __restrict__ x0,
                                 float* __restrict__ out) {
    int i = blockIdx.x * blockDim.x + threadIdx.x;
    if (i < Nn * IOd) {
        int f = i % IOd;
        float v = (g_h[i] - g_mean[f]) * g_inv[f] * gam[f] + bet[f] + x0[i];
        out[i] = v > 0.f ? v : 0.f;
    }
}

// ---------------- launch sequence ----------------
extern "C" void kernel_launch(void* const* d_in, const int* in_sizes, int n_in,
                              void* d_out, int out_size) {
    const float* x0  = (const float*)d_in[0];
    const void*  edg = d_in[1];
    const float* b1  = (const float*)d_in[6];
    const float* g1  = (const float*)d_in[7];
    const float* be1 = (const float*)d_in[8];
    const float* b2  = (const float*)d_in[13];
    const float* g2  = (const float*)d_in[14];
    const float* be2 = (const float*)d_in[15];
    float* out = (float*)d_out;

    W8 ws;
    ws.w[0] = (const float*)d_in[2];
    ws.w[1] = (const float*)d_in[3];
    ws.w[2] = (const float*)d_in[4];
    ws.w[3] = (const float*)d_in[5];
    ws.w[4] = (const float*)d_in[9];
    ws.w[5] = (const float*)d_in[10];
    ws.w[6] = (const float*)d_in[11];
    ws.w[7] = (const float*)d_in[12];

    __half *pqh, *pkh, *pvh;
    float *pr, *px1, *pwt;
    cudaGetSymbolAddress((void**)&pqh, g_qh);
    cudaGetSymbolAddress((void**)&pkh, g_kh);
    cudaGetSymbolAddress((void**)&pvh, g_vh);
    cudaGetSymbolAddress((void**)&pr,  g_r);
    cudaGetSymbolAddress((void**)&px1, g_x1);
    cudaGetSymbolAddress((void**)&pwt, g_wt);

    const int SMEM_GEMM = 4 * 128 * SROW * 4;
    cudaFuncSetAttribute((const void*)fused_gemm_kernel<1>, cudaFuncAttributeMaxDynamicSharedMemorySize, SMEM_GEMM);
    cudaFuncSetAttribute((const void*)fused_gemm_kernel<2>, cudaFuncAttributeMaxDynamicSharedMemorySize, SMEM_GEMM);

    const int EDGE_BLOCKS = (Ee + 255) / 256;
    const int NODE_BLOCKS = (Nn + 255) / 256;
    const int NH_BLOCKS = (Nn * HIDd + 255) / 256;
    const int NI_BLOCKS = (Nn * IOd + 255) / 256;
    const int ATTN_BLOCKS = (Nn * 32 + 255) / 256;
    const int MB = (Nn + 127) / 128;

    // order chosen so fused_gemm<1> is launch index 3 (ncu profiles index 3)
    detect_zero_kernel<<<NODE_BLOCKS, 256>>>((const int*)edg);        // 0
    convert_count_kernel<<<EDGE_BLOCKS, 256>>>(edg);                  // 1
    transpose_all_kernel<<<1280, 256>>>(ws, pwt);                     // 2
    fused_gemm_kernel<1><<<dim3(MB, 8), 256, SMEM_GEMM>>>(x0, pwt + WT_L1, pqh, pkh, pvh, pr, Nn); // 3
    scan1_kernel<<<NB_SCAN, 1024>>>();                                // 4
    scan2_kernel<<<1, 1>>>();                                         // 5
    scan3_kernel<<<NB_SCAN, 1024>>>();                                // 6
    csr_scatter_kernel<<<EDGE_BLOCKS, 256>>>();                       // 7

    // ---- layer 1 ----
    attn_kernel<256><<<ATTN_BLOCKS, 256>>>(b1);
    bn_finalize_kernel<<<1, 256>>>(HIDd);
    bn_apply_relu_kernel<<<NH_BLOCKS, 256>>>(g1, be1, HIDd);

    // ---- layer 2 ----
    fused_gemm_kernel<2><<<dim3(MB, 6), 256, SMEM_GEMM>>>(px1, pwt + WT_L2, pqh, pkh, pvh, pr, Nn);
    attn_kernel<128><<<ATTN_BLOCKS, 256>>>(b2);
    bn_finalize_kernel<<<1, 256>>>(IOd);
    final_out_kernel<<<NI_BLOCKS, 256>>>(g2, be2, x0, out);
}

// round 10
// speedup vs baseline: 2.6256x; 1.0907x over previous
#include <cuda_runtime.h>
#include <cuda_fp16.h>
#include <math.h>
#include <stdint.h>

// Problem constants (fixed by the reference)
#define Nn   50000
#define Ee   800000
#define IOd  128
#define HIDd 256
#define KQd  256

// ---------------- device scratch (no allocations allowed) ----------------
__device__ __half g_qh[Nn * KQd];
__device__ __half g_kh[Nn * KQd];
__device__ __half g_vh[Nn * HIDd];
__device__ __half g_x0h[Nn * IOd];
__device__ __half g_x1h[Nn * HIDd];
__device__ float g_r[Nn * HIDd];
__device__ float g_h[Nn * HIDd];
__device__ __half g_wth[327680];    // transposed fp16 weights
__device__ int   g_src[Ee];
__device__ int   g_dst[Ee];
__device__ int   g_csr_src[Ee];
__device__ int   g_deg[Nn];
__device__ int   g_inc[Nn];
__device__ int   g_fill[Nn];
#define NB_SCAN 49
__device__ int   g_bsum[NB_SCAN];
__device__ int   g_boff[NB_SCAN];
__device__ float g_sumf[HIDd];      // zero at call entry; finalize re-zeros
__device__ float g_sumsqf[HIDd];
__device__ float g_mean[HIDd];
__device__ float g_inv[HIDd];
__device__ int   g_flag64[1];

#define WT_L1 0         // [1024 x 128]: Q1,K1,V1,R1
#define WT_L2 131072    // [768 x 256]:  Q2,K2,V2,R2

// ---------------- helpers ----------------
__device__ __forceinline__ uint32_t smem_u32(const void* p) {
    uint32_t a;
    asm("{ .reg .u64 t; cvta.to.shared.u64 t, %1; cvt.u32.u64 %0, t; }" : "=r"(a) : "l"(p));
    return a;
}
__device__ __forceinline__ void cp_async16(uint32_t sm, const void* g) {
    asm volatile("cp.async.cg.shared.global [%0], [%1], 16;" :: "r"(sm), "l"(g));
}
__device__ __forceinline__ void cp_commit() { asm volatile("cp.async.commit_group;"); }
__device__ __forceinline__ void cp_wait1() { asm volatile("cp.async.wait_group 1;"); }
__device__ __forceinline__ void cp_wait0() { asm volatile("cp.async.wait_group 0;"); }

// ---------------- prep: weight transpose->fp16 + x0->fp16 (one launch) -----
struct W8 { const float* w[8]; };
#define PREP_W 327680
#define PREP_TOTAL (PREP_W + Nn * IOd)
__global__ void prep_kernel(W8 ws, const float* __restrict__ x0,
                            __half* __restrict__ Wt, __half* __restrict__ x0h) {
    int i = blockIdx.x * 256 + threadIdx.x;
    if (i >= PREP_TOTAL) return;
    if (i < PREP_W) {
        int seg, base, K, N, dst;
        if (i < 131072)      { seg = i >> 15;       base = seg << 15;          K = 128; N = 256; dst = seg * 32768; }
        else if (i < 262144) { seg = 4 + ((i - 131072) >> 16); base = 131072 + ((seg - 4) << 16); K = 256; N = 256; dst = 131072 + (seg - 4) * 65536; }
        else                 { seg = 6 + ((i - 262144) >> 15); base = 262144 + ((seg - 6) << 15); K = 256; N = 128; dst = 262144 + (seg - 6) * 32768; }
        int il = i - base;
        int k = il / N, n = il % N;
        Wt[dst + n * K + k] = __float2half(ws.w[seg][il]);
    } else {
        int j = i - PREP_W;
        x0h[j] = __float2half(x0[j]);
    }
}

// ---------------- fused HMMA fp16 GEMM (4 outputs per layer) ----------------
// CTA tile 128x128, 8 warps (2M x 4N), warp tile 64x32, mma.m16n8k16.f16.
// SMEM rows padded to 72 halves (144B) -> conflict-free fragment loads.
#define SROWH 72

template <int LAYER>
__global__ __launch_bounds__(256) void fused_gemm_kernel(
    const __half* __restrict__ A, const __half* __restrict__ BtAll,
    __half* __restrict__ Oq, __half* __restrict__ Ok,
    __half* __restrict__ Ov, float* __restrict__ Or, int M)
{
    constexpr int K = (LAYER == 1) ? 128 : 256;
    extern __shared__ __half smem[];
    __half* As = smem;                      // 2 x 128 x SROWH halves
    __half* Bs = smem + 2 * 128 * SROWH;

    const int tid = threadIdx.x;
    const int wid = tid >> 5;
    const int lane = tid & 31;
    const int gID = lane >> 2;
    const int tig = lane & 3;
    const int wm = (wid & 1) * 64;
    const int wn = (wid >> 1) * 32;
    const int m0 = blockIdx.x * 128;
    const int y = blockIdx.y;
    const int nb0 = y * 128;

    float c[4][4][4] = {};
    constexpr int NC = K / 64;      // 64-half K chunks

    auto stage = [&](int cc, int buf) {
        const int k0 = cc * 64;
        __half* ab = As + buf * (128 * SROWH);
        __half* bb = Bs + buf * (128 * SROWH);
        #pragma unroll
        for (int i = 0; i < 4; i++) {           // A: 128 rows x 64 halves (128B/row)
            int idx = tid + i * 256;
            int row = idx >> 3, g = idx & 7;
            int gr = m0 + row; if (gr >= M) gr = M - 1;
            cp_async16(smem_u32(ab + row * SROWH + g * 8), A + (size_t)gr * K + k0 + g * 8);
        }
        #pragma unroll
        for (int i = 0; i < 4; i++) {           // B: 128 rows x 64 halves
            int idx = tid + i * 256;
            int row = idx >> 3, g = idx & 7;
            cp_async16(smem_u32(bb + row * SROWH + g * 8), BtAll + (size_t)(nb0 + row) * K + k0 + g * 8);
        }
        cp_commit();
    };

    stage(0, 0);
    for (int cc = 0; cc < NC; cc++) {
        const int buf = cc & 1;
        if (cc + 1 < NC) { stage(cc + 1, buf ^ 1); cp_wait1(); }
        else             { cp_wait0(); }
        __syncthreads();

        const __half* ab = As + buf * (128 * SROWH);
        const __half* bb = Bs + buf * (128 * SROWH);

        #pragma unroll
        for (int ks = 0; ks < 4; ks++) {        // 4 ksteps of 16 halves
            const int kk = ks * 16;
            uint32_t af[4][4];
            #pragma unroll
            for (int mf = 0; mf < 4; mf++) {
                const __half* base = ab + (wm + mf * 16) * SROWH + kk + tig * 2;
                af[mf][0] = *(const uint32_t*)(base + gID * SROWH);
                af[mf][1] = *(const uint32_t*)(base + (gID + 8) * SROWH);
                af[mf][2] = *(const uint32_t*)(base + gID * SROWH + 8);
                af[mf][3] = *(const uint32_t*)(base + (gID + 8) * SROWH + 8);
            }
            uint32_t bf[4][2];
            #pragma unroll
            for (int nf = 0; nf < 4; nf++) {
                const __half* base = bb + (wn + nf * 8 + gID) * SROWH + kk + tig * 2;
                bf[nf][0] = *(const uint32_t*)(base);
                bf[nf][1] = *(const uint32_t*)(base + 8);
            }
            #pragma unroll
            for (int mf = 0; mf < 4; mf++)
                #pragma unroll
                for (int nf = 0; nf < 4; nf++)
                    asm volatile(
                        "mma.sync.aligned.m16n8k16.row.col.f32.f16.f16.f32 "
                        "{%0,%1,%2,%3}, {%4,%5,%6,%7}, {%8,%9}, {%0,%1,%2,%3};"
                        : "+f"(c[mf][nf][0]), "+f"(c[mf][nf][1]),
                          "+f"(c[mf][nf][2]), "+f"(c[mf][nf][3])
                        : "r"(af[mf][0]), "r"(af[mf][1]), "r"(af[mf][2]), "r"(af[mf][3]),
                          "r"(bf[nf][0]), "r"(bf[nf][1]));
        }
        __syncthreads();
    }

    __half* hout = nullptr; float* fout = nullptr;
    int Nout, cb;
    if (LAYER == 1) {
        int oi = y >> 1; cb = (y & 1) * 128; Nout = 256;
        if (oi == 0) hout = Oq; else if (oi == 1) hout = Ok;
        else if (oi == 2) hout = Ov; else fout = Or;
    } else {
        if (y < 4) { int oi = y >> 1; cb = (y & 1) * 128; Nout = 256; hout = (oi == 0) ? Oq : Ok; }
        else       { cb = 0; Nout = 128; if (y == 4) hout = Ov; else fout = Or; }
    }

    #pragma unroll
    for (int mf = 0; mf < 4; mf++) {
        int row = m0 + wm + mf * 16 + gID;
        #pragma unroll
        for (int nf = 0; nf < 4; nf++) {
            int col = cb + wn + nf * 8 + tig * 2;
            if (hout) {
                if (row < M)
                    *(__half2*)(hout + (size_t)row * Nout + col) = __floats2half2_rn(c[mf][nf][0], c[mf][nf][1]);
                if (row + 8 < M)
                    *(__half2*)(hout + (size_t)(row + 8) * Nout + col) = __floats2half2_rn(c[mf][nf][2], c[mf][nf][3]);
            } else {
                if (row < M)
                    *(float2*)(fout + (size_t)row * Nout + col) = make_float2(c[mf][nf][0], c[mf][nf][1]);
                if (row + 8 < M)
                    *(float2*)(fout + (size_t)(row + 8) * Nout + col) = make_float2(c[mf][nf][2], c[mf][nf][3]);
            }
        }
    }
}

// ---------------- setup: zero + edge dtype detect ----------------
__global__ void detect_zero_kernel(const int* __restrict__ ew) {
    int i = blockIdx.x * blockDim.x + threadIdx.x;
    if (i < Nn) { g_deg[i] = 0; g_fill[i] = 0; }
    if (blockIdx.x == 0) {
        __shared__ int nz;
        if (threadIdx.x == 0) nz = 0;
        __syncthreads();
        int stride = Ee / 256;
        int idx = 2 * (threadIdx.x * stride) + 1;
        if (ew[idx] != 0) atomicOr(&nz, 1);
        __syncthreads();
        if (threadIdx.x == 0) g_flag64[0] = nz ? 0 : 1;
    }
}

__global__ void convert_count_kernel(const void* __restrict__ edges) {
    int e = blockIdx.x * blockDim.x + threadIdx.x;
    if (e >= Ee) return;
    int s, d;
    if (g_flag64[0]) {
        const long long* p = (const long long*)edges;
        s = (int)p[e]; d = (int)p[Ee + e];
    } else {
        const int* p = (const int*)edges;
        s = p[e]; d = p[Ee + e];
    }
    g_src[e] = s; g_dst[e] = d;
    atomicAdd(&g_deg[d], 1);
}

// ---------------- CSR scan + scatter ----------------
__global__ void scan1_kernel() {
    __shared__ int sm[1024];
    int i = blockIdx.x * 1024 + threadIdx.x;
    int v = (i < Nn) ? g_deg[i] : 0;
    sm[threadIdx.x] = v;
    __syncthreads();
    for (int off = 1; off < 1024; off <<= 1) {
        int t = (threadIdx.x >= off) ? sm[threadIdx.x - off] : 0;
        __syncthreads();
        sm[threadIdx.x] += t;
        __syncthreads();
    }
    if (i < Nn) g_inc[i] = sm[threadIdx.x];
    if (threadIdx.x == 1023) g_bsum[blockIdx.x] = sm[1023];
}
__global__ void scan2_kernel() {
    // 64-thread inclusive scan over NB_SCAN block sums -> exclusive offsets
    __shared__ int sm[64];
    int t = threadIdx.x;
    sm[t] = (t < NB_SCAN) ? g_bsum[t] : 0;
    __syncthreads();
    #pragma unroll
    for (int off = 1; off < 64; off <<= 1) {
        int v = (t >= off) ? sm[t - off] : 0;
        __syncthreads();
        sm[t] += v;
        __syncthreads();
    }
    if (t < NB_SCAN) g_boff[t] = sm[t] - g_bsum[t];
}
__global__ void scan3_kernel() {
    int i = blockIdx.x * 1024 + threadIdx.x;
    if (i < Nn) g_inc[i] += g_boff[blockIdx.x];
}
__global__ void csr_scatter_kernel() {
    int e = blockIdx.x * blockDim.x + threadIdx.x;
    if (e >= Ee) return;
    int d = g_dst[e];
    int pos = g_inc[d] - g_deg[d] + atomicAdd(&g_fill[d], 1);
    g_csr_src[pos] = g_src[e];
}

// ---------------- attention: online softmax, unroll 4, fused BN stats ------
__device__ __forceinline__ float dot8h(uint4 a, uint4 b) {
    const __half2* ah = (const __half2*)&a;
    const __half2* bh = (const __half2*)&b;
    float p = 0.f;
    #pragma unroll
    for (int i = 0; i < 4; i++) {
        float2 fa = __half22float2(ah[i]);
        float2 fb = __half22float2(bh[i]);
        p += fa.x * fb.x + fa.y * fb.y;
    }
    return p;
}
__device__ __forceinline__ void unpack8h(uint4 a, float* f) {
    const __half2* ah = (const __half2*)&a;
    #pragma unroll
    for (int i = 0; i < 4; i++) {
        float2 t = __half22float2(ah[i]);
        f[2 * i] = t.x; f[2 * i + 1] = t.y;
    }
}
__device__ __forceinline__ void unpack4h(uint2 a, float* f) {
    const __half2* ah = (const __half2*)&a;
    #pragma unroll
    for (int i = 0; i < 2; i++) {
        float2 t = __half22float2(ah[i]);
        f[2 * i] = t.x; f[2 * i + 1] = t.y;
    }
}

template <int F>
__global__ __launch_bounds__(256) void attn_kernel(const float* __restrict__ bias) {
    __shared__ float ssum[F], ssq[F];
    int tid = threadIdx.x;
    int n = (blockIdx.x * blockDim.x + tid) >> 5;
    int lane = tid & 31;
    if (tid < F) { ssum[tid] = 0.f; ssq[tid] = 0.f; }
    __syncthreads();

    constexpr int EPL = F / 32;
    float hv[EPL];

    if (n < Nn) {
        int deg = g_deg[n];
        int base = g_inc[n] - deg;

        const uint4* qh = (const uint4*)g_qh;
        const uint4* kh = (const uint4*)g_kh;
        float acc[EPL];
        #pragma unroll
        for (int i = 0; i < EPL; i++) acc[i] = 0.f;
        float ssm = 0.f;

        if (deg > 0) {
            uint4 qreg = qh[(size_t)n * 32 + lane];
            float mx = -INFINITY;
            int j = 0;
            for (; j + 4 <= deg; j += 4) {
                int s0 = g_csr_src[base + j];
                int s1 = g_csr_src[base + j + 1];
                int s2 = g_csr_src[base + j + 2];
                int s3 = g_csr_src[base + j + 3];
                float p0 = dot8h(qreg, kh[(size_t)s0 * 32 + lane]);
                float p1 = dot8h(qreg, kh[(size_t)s1 * 32 + lane]);
                float p2 = dot8h(qreg, kh[(size_t)s2 * 32 + lane]);
                float p3 = dot8h(qreg, kh[(size_t)s3 * 32 + lane]);
                #pragma unroll
                for (int off = 16; off; off >>= 1) {
                    p0 += __shfl_xor_sync(0xffffffffu, p0, off);
                    p1 += __shfl_xor_sync(0xffffffffu, p1, off);
                    p2 += __shfl_xor_sync(0xffffffffu, p2, off);
                    p3 += __shfl_xor_sync(0xffffffffu, p3, off);
                }
                p0 *= 0.0625f; p1 *= 0.0625f; p2 *= 0.0625f; p3 *= 0.0625f;
                float v0[EPL], v1[EPL], v2[EPL], v3[EPL];
                if (F == 256) {
                    unpack8h(((const uint4*)g_vh)[(size_t)s0 * 32 + lane], v0);
                    unpack8h(((const uint4*)g_vh)[(size_t)s1 * 32 + lane], v1);
                    unpack8h(((const uint4*)g_vh)[(size_t)s2 * 32 + lane], v2);
                    unpack8h(((const uint4*)g_vh)[(size_t)s3 * 32 + lane], v3);
                } else {
                    unpack4h(((const uint2*)g_vh)[(size_t)s0 * 32 + lane], v0);
                    unpack4h(((const uint2*)g_vh)[(size_t)s1 * 32 + lane], v1);
                    unpack4h(((const uint2*)g_vh)[(size_t)s2 * 32 + lane], v2);
                    unpack4h(((const uint2*)g_vh)[(size_t)s3 * 32 + lane], v3);
                }
                float mnew = fmaxf(fmaxf(mx, fmaxf(p0, p1)), fmaxf(p2, p3));
                float corr = expf(mx - mnew);
                float e0 = expf(p0 - mnew);
                float e1 = expf(p1 - mnew);
                float e2 = expf(p2 - mnew);
                float e3 = expf(p3 - mnew);
                ssm = ssm * corr + e0 + e1 + e2 + e3;
                #pragma unroll
                for (int i = 0; i < EPL; i++)
                    acc[i] = acc[i] * corr + e0 * v0[i] + e1 * v1[i] + e2 * v2[i] + e3 * v3[i];
                mx = mnew;
            }
            for (; j < deg; j++) {
                int s0 = g_csr_src[base + j];
                float p0 = dot8h(qreg, kh[(size_t)s0 * 32 + lane]);
                #pragma unroll
                for (int off = 16; off; off >>= 1)
                    p0 += __shfl_xor_sync(0xffffffffu, p0, off);
                p0 *= 0.0625f;
                float v0[EPL];
                if (F == 256) unpack8h(((const uint4*)g_vh)[(size_t)s0 * 32 + lane], v0);
                else          unpack4h(((const uint2*)g_vh)[(size_t)s0 * 32 + lane], v0);
                float mnew = fmaxf(mx, p0);
                float corr = expf(mx - mnew);
                float e0 = expf(p0 - mnew);
                ssm = ssm * corr + e0;
                #pragma unroll
                for (int i = 0; i < EPL; i++)
                    acc[i] = acc[i] * corr + e0 * v0[i];
                mx = mnew;
            }
        }

        float inv = (deg > 0) ? 1.f / fmaxf(ssm, 1e-16f) : 0.f;
        const float4* r4 = (const float4*)g_r;
        const float4* b4 = (const float4*)bias;
        float4* h4 = (float4*)g_h;
        size_t o = (size_t)n * (F / 4) + lane * (EPL / 4);
        int bo = lane * (EPL / 4);
        #pragma unroll
        for (int t = 0; t < EPL / 4; t++) {
            float4 rr = r4[o + t], bb = b4[bo + t];
            hv[4 * t + 0] = acc[4 * t + 0] * inv + rr.x + bb.x;
            hv[4 * t + 1] = acc[4 * t + 1] * inv + rr.y + bb.y;
            hv[4 * t + 2] = acc[4 * t + 2] * inv + rr.z + bb.z;
            hv[4 * t + 3] = acc[4 * t + 3] * inv + rr.w + bb.w;
            h4[o + t] = make_float4(hv[4 * t + 0], hv[4 * t + 1], hv[4 * t + 2], hv[4 * t + 3]);
        }
        #pragma unroll
        for (int i = 0; i < EPL; i++) {
            int f = lane * EPL + i;
            atomicAdd(&ssum[f], hv[i]);
            atomicAdd(&ssq[f], hv[i] * hv[i]);
        }
    }
    __syncthreads();
    if (tid < F) {
        atomicAdd(&g_sumf[tid], ssum[tid]);
        atomicAdd(&g_sumsqf[tid], ssq[tid]);
    }
}

// ---------------- batch norm finalize / apply ----------------
__global__ void bn_finalize_kernel(int F) {
    int f = threadIdx.x;
    if (f < F) {
        double mu = (double)g_sumf[f] / (double)Nn;
        double var = (double)g_sumsqf[f] / (double)Nn - mu * mu;
        if (var < 0.0) var = 0.0;
        g_mean[f] = (float)mu;
        g_inv[f] = (float)(1.0 / sqrt(var + 1e-5));
    }
    g_sumf[f] = 0.f;
    g_sumsqf[f] = 0.f;
}
// writes fp16 x1 (input to layer-2 GEMM)
__global__ void bn_apply_relu_kernel(const float* __restrict__ gam,
                                     const float* __restrict__ bet,
                                     __half* __restrict__ x1h, int F) {
    int i = blockIdx.x * blockDim.x + threadIdx.x;
    if (i < Nn * F) {
        int f = i % F;
        float v = (g_h[i] - g_mean[f]) * g_inv[f] * gam[f] + bet[f];
        x1h[i] = __float2half(v > 0.f ? v : 0.f);
    }
}
__global__ void final_out_kernel(const float* __restrict__ gam,
                                 const float* __restrict__ bet,
                                 const float* __restrict__ x0,
                                 float* __restrict__ out) {
    int i = blockIdx.x * blockDim.x + threadIdx.x;
    if (i < Nn * IOd) {
        int f = i % IOd;
        float v = (g_h[i] - g_mean[f]) * g_inv[f] * gam[f] + bet[f] + x0[i];
        out[i] = v > 0.f ? v : 0.f;
    }
}

// ---------------- launch sequence ----------------
extern "C" void kernel_launch(void* const* d_in, const int* in_sizes, int n_in,
                              void* d_out, int out_size) {
    const float* x0  = (const float*)d_in[0];
    const void*  edg = d_in[1];
    const float* b1  = (const float*)d_in[6];
    const float* g1  = (const float*)d_in[7];
    const float* be1 = (const float*)d_in[8];
    const float* b2  = (const float*)d_in[13];
    const float* g2  = (const float*)d_in[14];
    const float* be2 = (const float*)d_in[15];
    float* out = (float*)d_out;

    W8 ws;
    ws.w[0] = (const float*)d_in[2];
    ws.w[1] = (const float*)d_in[3];
    ws.w[2] = (const float*)d_in[4];
    ws.w[3] = (const float*)d_in[5];
    ws.w[4] = (const float*)d_in[9];
    ws.w[5] = (const float*)d_in[10];
    ws.w[6] = (const float*)d_in[11];
    ws.w[7] = (const float*)d_in[12];

    __half *pqh, *pkh, *pvh, *px0h, *px1h, *pwth;
    float *pr;
    cudaGetSymbolAddress((void**)&pqh,  g_qh);
    cudaGetSymbolAddress((void**)&pkh,  g_kh);
    cudaGetSymbolAddress((void**)&pvh,  g_vh);
    cudaGetSymbolAddress((void**)&px0h, g_x0h);
    cudaGetSymbolAddress((void**)&px1h, g_x1h);
    cudaGetSymbolAddress((void**)&pwth, g_wth);
    cudaGetSymbolAddress((void**)&pr,   g_r);

    const int SMEM_GEMM = 4 * 128 * SROWH * 2;   // 73728 bytes
    cudaFuncSetAttribute((const void*)fused_gemm_kernel<1>, cudaFuncAttributeMaxDynamicSharedMemorySize, SMEM_GEMM);
    cudaFuncSetAttribute((const void*)fused_gemm_kernel<2>, cudaFuncAttributeMaxDynamicSharedMemorySize, SMEM_GEMM);

    const int EDGE_BLOCKS = (Ee + 255) / 256;
    const int NODE_BLOCKS = (Nn + 255) / 256;
    const int NH_BLOCKS = (Nn * HIDd + 255) / 256;
    const int NI_BLOCKS = (Nn * IOd + 255) / 256;
    const int ATTN_BLOCKS = (Nn * 32 + 255) / 256;
    const int MB = (Nn + 127) / 128;
    const int PREP_BLOCKS = (PREP_TOTAL + 255) / 256;

    // order keeps fused_gemm<1> at launch index 3 (ncu profiles index 3)
    detect_zero_kernel<<<NODE_BLOCKS, 256>>>((const int*)edg);        // 0
    convert_count_kernel<<<EDGE_BLOCKS, 256>>>(edg);                  // 1
    prep_kernel<<<PREP_BLOCKS, 256>>>(ws, x0, pwth, px0h);            // 2
    fused_gemm_kernel<1><<<dim3(MB, 8), 256, SMEM_GEMM>>>(px0h, pwth + WT_L1, pqh, pkh, pvh, pr, Nn); // 3
    scan1_kernel<<<NB_SCAN, 1024>>>();                                // 4
    scan2_kernel<<<1, 64>>>();                                        // 5
    scan3_kernel<<<NB_SCAN, 1024>>>();                                // 6
    csr_scatter_kernel<<<EDGE_BLOCKS, 256>>>();                       // 7

    // ---- layer 1 ----
    attn_kernel<256><<<ATTN_BLOCKS, 256>>>(b1);
    bn_finalize_kernel<<<1, 256>>>(HIDd);
    bn_apply_relu_kernel<<<NH_BLOCKS, 256>>>(g1, be1, px1h, HIDd);

    // ---- layer 2 ----
    fused_gemm_kernel<2><<<dim3(MB, 6), 256, SMEM_GEMM>>>(px1h, pwth + WT_L2, pqh, pkh, pvh, pr, Nn);
    attn_kernel<128><<<ATTN_BLOCKS, 256>>>(b2);
    bn_finalize_kernel<<<1, 256>>>(IOd);
    final_out_kernel<<<NI_BLOCKS, 256>>>(g2, be2, x0, out);
}